// round 1
// baseline (speedup 1.0000x reference)
#include <cuda_runtime.h>
#include <cstdint>
#include <cstddef>

#define NN 8192
#define FIN 512
#define FH 64
#define NHEAD 4
#define NCLS 20
#define THRESH 20.0f

// ---------------- scratch (device globals; no allocations) ----------------
__device__ float g_Wh1[NHEAD][NN][FH];        // 8 MB
__device__ float g_src1[NHEAD][NN];
__device__ float g_dst1[NHEAD][NN];
__device__ float g_m1[NHEAD][NN];
__device__ float g_h1[NN][NHEAD * FH];        // 8 MB
__device__ unsigned g_mask[NN][NN / 32];      // 8 MB bitmask
__device__ float g_Wh2[NN][NCLS];
__device__ float g_src2[NN];
__device__ float g_dst2[NN];
__device__ float g_m2[NN];

// ---------------- 1) adjacency -> bitmask ----------------
__global__ void k_mask(const int* __restrict__ adj) {
    int word = blockIdx.x * 8 + (threadIdx.x >> 5);
    int lane = threadIdx.x & 31;
    size_t idx = (size_t)word * 32 + lane;
    int a = adj[idx];
    unsigned b = __ballot_sync(0xffffffffu, a > 0);
    if (lane == 0) ((unsigned*)g_mask)[word] = b;
}

// ---------------- 2) Wh1[h] = x @ W1[h]  (8192x512 @ 512x64) ----------------
#define BM 128
#define BK 16
__global__ __launch_bounds__(256) void k_gemm1(const float* __restrict__ x,
                                               const float* __restrict__ W1) {
    int h = blockIdx.y;
    int m0 = blockIdx.x * BM;
    __shared__ float As[BK][BM];
    __shared__ float Bs[BK][FH];
    const float* W = W1 + (size_t)h * FIN * FH;
    int tid = threadIdx.x;
    int tr = tid >> 4, tc = tid & 15;   // 16x16 threads: 8 rows x 4 cols each
    float acc[8][4];
#pragma unroll
    for (int i = 0; i < 8; i++)
#pragma unroll
        for (int j = 0; j < 4; j++) acc[i][j] = 0.f;

    for (int k0 = 0; k0 < FIN; k0 += BK) {
#pragma unroll
        for (int i = 0; i < 2; i++) {
            int q = tid + i * 256;               // float4 index, 512 total
            int row = q >> 2; int c4 = (q & 3) * 4;
            float4 v = *(const float4*)&x[(size_t)(m0 + row) * FIN + k0 + c4];
            As[c4 + 0][row] = v.x; As[c4 + 1][row] = v.y;
            As[c4 + 2][row] = v.z; As[c4 + 3][row] = v.w;
        }
        {
            int row = tid >> 4, c4 = (tid & 15) * 4;
            float4 v = *(const float4*)&W[(size_t)(k0 + row) * FH + c4];
            *(float4*)&Bs[row][c4] = v;
        }
        __syncthreads();
#pragma unroll
        for (int k = 0; k < BK; k++) {
            float a[8], b[4];
#pragma unroll
            for (int i = 0; i < 8; i++) a[i] = As[k][tr * 8 + i];
#pragma unroll
            for (int j = 0; j < 4; j++) b[j] = Bs[k][tc * 4 + j];
#pragma unroll
            for (int i = 0; i < 8; i++)
#pragma unroll
                for (int j = 0; j < 4; j++) acc[i][j] += a[i] * b[j];
        }
        __syncthreads();
    }
#pragma unroll
    for (int i = 0; i < 8; i++) {
        int row = m0 + tr * 8 + i;
        float4 v = make_float4(acc[i][0], acc[i][1], acc[i][2], acc[i][3]);
        *(float4*)&g_Wh1[h][row][tc * 4] = v;
    }
}

// ---------------- 3) src1/dst1 = Wh1 . alpha ----------------
__global__ void k_srcdst1(const float* __restrict__ alpha1) {
    int wid = blockIdx.x * 8 + (threadIdx.x >> 5);
    int lane = threadIdx.x & 31;
    int h = wid >> 13;
    int i = wid & (NN - 1);
    const float* a = alpha1 + h * 2 * FH;
    float w0 = g_Wh1[h][i][lane], w1 = g_Wh1[h][i][lane + 32];
    float s = w0 * a[lane] + w1 * a[lane + 32];
    float d = w0 * a[FH + lane] + w1 * a[FH + lane + 32];
#pragma unroll
    for (int o = 16; o; o >>= 1) {
        s += __shfl_xor_sync(0xffffffffu, s, o);
        d += __shfl_xor_sync(0xffffffffu, d, o);
    }
    if (!lane) { g_src1[h][i] = s; g_dst1[h][i] = d; }
}

// ---------------- 4) layer-1 masked row max (all 4 heads fused) ----------------
__global__ __launch_bounds__(256) void k_max1() {
    __shared__ float sd[NHEAD][2048];
    int warp = threadIdx.x >> 5, lane = threadIdx.x & 31;
    int row = blockIdx.x * 8 + warp;
    float s0 = g_src1[0][row], s1 = g_src1[1][row], s2 = g_src1[2][row], s3 = g_src1[3][row];
    float m0 = -3e38f, m1 = -3e38f, m2 = -3e38f, m3 = -3e38f;
    for (int c0 = 0; c0 < NN; c0 += 2048) {
        for (int q = threadIdx.x; q < NHEAD * 2048; q += 256) {
            int hh = q >> 11; int jj = q & 2047;
            sd[hh][jj] = g_dst1[hh][c0 + jj];
        }
        __syncthreads();
        for (int it = 0; it < 64; it++) {
            unsigned w = g_mask[row][(c0 >> 5) + it];
            int j = it * 32 + lane;
            float d0 = sd[0][j], d1 = sd[1][j], d2 = sd[2][j], d3 = sd[3][j];
            if ((w >> lane) & 1) {
                float v;
                v = s0 + d0; m0 = fmaxf(m0, fmaxf(v, 0.2f * v));
                v = s1 + d1; m1 = fmaxf(m1, fmaxf(v, 0.2f * v));
                v = s2 + d2; m2 = fmaxf(m2, fmaxf(v, 0.2f * v));
                v = s3 + d3; m3 = fmaxf(m3, fmaxf(v, 0.2f * v));
            }
        }
        __syncthreads();
    }
#pragma unroll
    for (int o = 16; o; o >>= 1) {
        m0 = fmaxf(m0, __shfl_xor_sync(0xffffffffu, m0, o));
        m1 = fmaxf(m1, __shfl_xor_sync(0xffffffffu, m1, o));
        m2 = fmaxf(m2, __shfl_xor_sync(0xffffffffu, m2, o));
        m3 = fmaxf(m3, __shfl_xor_sync(0xffffffffu, m3, o));
    }
    if (!lane) {
        g_m1[0][row] = m0; g_m1[1][row] = m1; g_m1[2][row] = m2; g_m1[3][row] = m3;
    }
}

// ---------------- 5) layer-1 thresholded softmax-accumulate ----------------
#define JT 64
__global__ __launch_bounds__(512) void k_att1() {
    int h = blockIdx.y;
    int warp = threadIdx.x >> 5, lane = threadIdx.x & 31;
    int row0 = blockIdx.x * 64 + warp * 4;
    __shared__ float sv[JT][64];
    __shared__ float sdst[JT];
    float src[4], m[4], acc0[4], acc1[4], ssum[4];
#pragma unroll
    for (int r = 0; r < 4; r++) {
        src[r] = g_src1[h][row0 + r];
        m[r] = g_m1[h][row0 + r];
        acc0[r] = 0.f; acc1[r] = 0.f; ssum[r] = 0.f;
    }
    const float* V = &g_Wh1[h][0][0];
    for (int t = 0; t < NN; t += JT) {
#pragma unroll
        for (int i = 0; i < 2; i++) {
            int q = threadIdx.x + i * 512;       // float4 index, 1024 total
            int jj = q >> 4; int c = (q & 15) * 4;
            *(float4*)&sv[jj][c] = *(const float4*)&V[(size_t)(t + jj) * FH + c];
        }
        if (threadIdx.x < JT) sdst[threadIdx.x] = g_dst1[h][t + threadIdx.x];
        __syncthreads();
#pragma unroll
        for (int sub = 0; sub < JT / 32; sub++) {
            float dv = sdst[sub * 32 + lane];
#pragma unroll
            for (int r = 0; r < 4; r++) {
                unsigned w = g_mask[row0 + r][(t + sub * 32) >> 5];
                float v = src[r] + dv;
                float e = fmaxf(v, 0.2f * v);
                bool sig = ((w >> lane) & 1) && (e > m[r] - THRESH);
                float p = sig ? __expf(e - m[r]) : 0.0f;
                ssum[r] += p;
                unsigned ball = __ballot_sync(0xffffffffu, p > 0.0f);
                while (ball) {
                    int L = __ffs(ball) - 1; ball &= ball - 1;
                    float pb = __shfl_sync(0xffffffffu, p, L);
                    int jj = sub * 32 + L;
                    acc0[r] += pb * sv[jj][lane];
                    acc1[r] += pb * sv[jj][lane + 32];
                }
            }
        }
        __syncthreads();
    }
#pragma unroll
    for (int r = 0; r < 4; r++) {
        float s = ssum[r];
#pragma unroll
        for (int o = 16; o; o >>= 1) s += __shfl_xor_sync(0xffffffffu, s, o);
        float inv = 1.0f / s;
        float o0 = acc0[r] * inv, o1 = acc1[r] * inv;
        o0 = o0 > 0.f ? o0 : expm1f(o0);
        o1 = o1 > 0.f ? o1 : expm1f(o1);
        int row = row0 + r;
        g_h1[row][h * FH + lane] = o0;
        g_h1[row][h * FH + 32 + lane] = o1;
    }
}

// ---------------- 6) Wh2 = h1 @ W2 (+ src2/dst2) ----------------
__global__ __launch_bounds__(256) void k_gemm2(const float* __restrict__ W2,
                                               const float* __restrict__ alpha2) {
    __shared__ float sW[256][21];
    __shared__ float sa[40];
    int tid = threadIdx.x;
    for (int q = tid; q < 256 * NCLS; q += 256) sW[q / NCLS][q % NCLS] = W2[q];
    if (tid < 40) sa[tid] = alpha2[tid];
    __syncthreads();
    int lane = tid & 31, warp = tid >> 5;
    int row = blockIdx.x * 8 + warp;
    float acc[NCLS];
#pragma unroll
    for (int c = 0; c < NCLS; c++) acc[c] = 0.f;
    for (int k = lane; k < 256; k += 32) {
        float hv = g_h1[row][k];
#pragma unroll
        for (int c = 0; c < NCLS; c++) acc[c] += hv * sW[k][c];
    }
#pragma unroll
    for (int c = 0; c < NCLS; c++)
#pragma unroll
        for (int o = 16; o; o >>= 1) acc[c] += __shfl_xor_sync(0xffffffffu, acc[c], o);
    if (lane == 0) {
        float s = 0.f, d = 0.f;
#pragma unroll
        for (int c = 0; c < NCLS; c++) {
            g_Wh2[row][c] = acc[c];
            s += acc[c] * sa[c];
            d += acc[c] * sa[NCLS + c];
        }
        g_src2[row] = s; g_dst2[row] = d;
    }
}

// ---------------- 7) layer-2 masked row max ----------------
__global__ __launch_bounds__(256) void k_max2() {
    __shared__ float sd[2048];
    int warp = threadIdx.x >> 5, lane = threadIdx.x & 31;
    int row = blockIdx.x * 8 + warp;
    float s = g_src2[row];
    float m = -3e38f;
    for (int c0 = 0; c0 < NN; c0 += 2048) {
        for (int q = threadIdx.x; q < 2048; q += 256) sd[q] = g_dst2[c0 + q];
        __syncthreads();
        for (int it = 0; it < 64; it++) {
            unsigned w = g_mask[row][(c0 >> 5) + it];
            float d = sd[it * 32 + lane];
            if ((w >> lane) & 1) {
                float v = s + d;
                m = fmaxf(m, fmaxf(v, 0.2f * v));
            }
        }
        __syncthreads();
    }
#pragma unroll
    for (int o = 16; o; o >>= 1) m = fmaxf(m, __shfl_xor_sync(0xffffffffu, m, o));
    if (!lane) g_m2[row] = m;
}

// ---------------- 8) layer-2 thresholded softmax-accumulate -> out ----------------
__global__ __launch_bounds__(256) void k_att2(float* __restrict__ out) {
    int warp = threadIdx.x >> 5, lane = threadIdx.x & 31;
    int row0 = blockIdx.x * 32 + warp * 4;
    __shared__ float sv[JT][32];   // padded to 32 (only [0..19] valid)
    __shared__ float sdst2[JT];
    float src[4], m[4], acc[4], ssum[4];
#pragma unroll
    for (int r = 0; r < 4; r++) {
        src[r] = g_src2[row0 + r];
        m[r] = g_m2[row0 + r];
        acc[r] = 0.f; ssum[r] = 0.f;
    }
    for (int t = 0; t < NN; t += JT) {
#pragma unroll
        for (int i = 0; i < 5; i++) {
            int q = threadIdx.x + i * 256;       // 1280 scalar loads
            int jj = q / NCLS; int c = q % NCLS;
            sv[jj][c] = g_Wh2[t + jj][c];
        }
        if (threadIdx.x < JT) sdst2[threadIdx.x] = g_dst2[t + threadIdx.x];
        __syncthreads();
#pragma unroll
        for (int sub = 0; sub < JT / 32; sub++) {
            float dv = sdst2[sub * 32 + lane];
#pragma unroll
            for (int r = 0; r < 4; r++) {
                unsigned w = g_mask[row0 + r][(t + sub * 32) >> 5];
                float v = src[r] + dv;
                float e = fmaxf(v, 0.2f * v);
                bool sig = ((w >> lane) & 1) && (e > m[r] - THRESH);
                float p = sig ? __expf(e - m[r]) : 0.0f;
                ssum[r] += p;
                unsigned ball = __ballot_sync(0xffffffffu, p > 0.0f);
                while (ball) {
                    int L = __ffs(ball) - 1; ball &= ball - 1;
                    float pb = __shfl_sync(0xffffffffu, p, L);
                    int jj = sub * 32 + L;
                    acc[r] += pb * sv[jj][lane];   // lanes >= 20 accumulate junk, unused
                }
            }
        }
        __syncthreads();
    }
#pragma unroll
    for (int r = 0; r < 4; r++) {
        float s = ssum[r];
#pragma unroll
        for (int o = 16; o; o >>= 1) s += __shfl_xor_sync(0xffffffffu, s, o);
        if (lane < NCLS) {
            float o0 = acc[r] / s;
            o0 = o0 > 0.f ? o0 : expm1f(o0);
            out[(size_t)(row0 + r) * NCLS + lane] = o0;
        }
    }
}

// ---------------- launch ----------------
extern "C" void kernel_launch(void* const* d_in, const int* in_sizes, int n_in,
                              void* d_out, int out_size) {
    const float* x      = (const float*)d_in[0];
    const int*   adj    = (const int*)d_in[1];
    const float* W1     = (const float*)d_in[2];
    const float* alpha1 = (const float*)d_in[3];
    const float* W2     = (const float*)d_in[4];
    const float* alpha2 = (const float*)d_in[5];
    float* out = (float*)d_out;

    k_mask<<<(NN * (NN / 32)) / 8, 256>>>(adj);
    k_gemm1<<<dim3(NN / BM, NHEAD), 256>>>(x, W1);
    k_srcdst1<<<NHEAD * NN / 8, 256>>>(alpha1);
    k_max1<<<NN / 8, 256>>>();
    k_att1<<<dim3(NN / 64, NHEAD), 512>>>();
    k_gemm2<<<NN / 8, 256>>>(W2, alpha2);
    k_max2<<<NN / 8, 256>>>();
    k_att2<<<NN / 32, 256>>>(out);
}

// round 3
// speedup vs baseline: 1.2615x; 1.2615x over previous
#include <cuda_runtime.h>
#include <cstdint>
#include <cstddef>

#define NN 8192
#define FIN 512
#define FH 64
#define NHEAD 4
#define NCLS 20
#define THRESH 18.0f

// ---------------- scratch (device globals; no allocations) ----------------
__device__ float g_Wh1[NHEAD][NN][FH];        // 8 MB
__device__ float g_src1[NHEAD][NN];
__device__ float g_dst1[NHEAD][NN];
__device__ float g_h1[NN][NHEAD * FH];        // 8 MB
__device__ unsigned g_mask[NN][NN / 32];      // 8 MB bitmask
__device__ float g_Wh2[NN][NCLS];
__device__ float g_src2[NN];
__device__ float g_dst2[NN];

// ---------------- tf32 mma helpers ----------------
__device__ __forceinline__ uint32_t f2tf32(float f) {
    uint32_t u;
    asm("cvt.rna.tf32.f32 %0, %1;" : "=r"(u) : "f"(f));
    return u;
}
__device__ __forceinline__ void tf32_split(float f, uint32_t& hi, uint32_t& lo) {
    hi = f2tf32(f);
    float r = f - __uint_as_float(hi);
    lo = f2tf32(r);
}
__device__ __forceinline__ void mma_tf32(float* d, const uint32_t* a, const uint32_t* b) {
    asm volatile(
        "mma.sync.aligned.m16n8k8.row.col.f32.tf32.tf32.f32 "
        "{%0,%1,%2,%3},{%4,%5,%6,%7},{%8,%9},{%0,%1,%2,%3};"
        : "+f"(d[0]), "+f"(d[1]), "+f"(d[2]), "+f"(d[3])
        : "r"(a[0]), "r"(a[1]), "r"(a[2]), "r"(a[3]), "r"(b[0]), "r"(b[1]));
}

// ---------------- 1) adjacency -> bitmask ----------------
__global__ void k_mask(const int* __restrict__ adj) {
    int word = blockIdx.x * 8 + (threadIdx.x >> 5);
    int lane = threadIdx.x & 31;
    size_t idx = (size_t)word * 32 + lane;
    int a = adj[idx];
    unsigned b = __ballot_sync(0xffffffffu, a > 0);
    if (lane == 0) ((unsigned*)g_mask)[word] = b;
}

// ---------------- 2) Wh1[h] = x @ W1[h] via tf32x2 mma (8192x512 @ 512x64) ----------------
__global__ __launch_bounds__(256) void k_gemm1(const float* __restrict__ x,
                                               const float* __restrict__ W1) {
    const int h = blockIdx.y;
    const int m0 = blockIdx.x * 128;
    __shared__ float As[128][36];   // 128x32 tile, padded
    __shared__ float Bs[32][68];    // 32x64 tile, padded
    const float* W = W1 + (size_t)h * FIN * FH;
    int tid = threadIdx.x, lane = tid & 31, warp = tid >> 5;
    int l4 = lane >> 2, lm4 = lane & 3;
    int wm = warp * 16;

    float d[8][4];
#pragma unroll
    for (int nt = 0; nt < 8; nt++)
#pragma unroll
        for (int i = 0; i < 4; i++) d[nt][i] = 0.f;

    for (int k0 = 0; k0 < FIN; k0 += 32) {
#pragma unroll
        for (int i = 0; i < 4; i++) {
            int idx = tid + i * 256;
            int row = idx >> 3, c = (idx & 7) * 4;
            float4 v = *(const float4*)&x[(size_t)(m0 + row) * FIN + k0 + c];
            *(float4*)&As[row][c] = v;
        }
#pragma unroll
        for (int i = 0; i < 2; i++) {
            int idx = tid + i * 256;
            int row = idx >> 4, c = (idx & 15) * 4;
            float4 v = *(const float4*)&W[(size_t)(k0 + row) * FH + c];
            *(float4*)&Bs[row][c] = v;
        }
        __syncthreads();
#pragma unroll
        for (int kk = 0; kk < 32; kk += 8) {
            float af[4];
            af[0] = As[wm + l4][kk + lm4];
            af[1] = As[wm + l4 + 8][kk + lm4];
            af[2] = As[wm + l4][kk + lm4 + 4];
            af[3] = As[wm + l4 + 8][kk + lm4 + 4];
            uint32_t ahi[4], alo[4];
#pragma unroll
            for (int i = 0; i < 4; i++) tf32_split(af[i], ahi[i], alo[i]);
#pragma unroll
            for (int nt = 0; nt < 8; nt++) {
                float bf[2];
                bf[0] = Bs[kk + lm4][nt * 8 + l4];
                bf[1] = Bs[kk + lm4 + 4][nt * 8 + l4];
                uint32_t bhi[2], blo[2];
                tf32_split(bf[0], bhi[0], blo[0]);
                tf32_split(bf[1], bhi[1], blo[1]);
                mma_tf32(d[nt], ahi, bhi);
                mma_tf32(d[nt], alo, bhi);
                mma_tf32(d[nt], ahi, blo);
            }
        }
        __syncthreads();
    }
#pragma unroll
    for (int nt = 0; nt < 8; nt++) {
        int r0 = m0 + wm + l4, c = nt * 8 + 2 * lm4;
        g_Wh1[h][r0][c]     = d[nt][0];
        g_Wh1[h][r0][c + 1] = d[nt][1];
        g_Wh1[h][r0 + 8][c]     = d[nt][2];
        g_Wh1[h][r0 + 8][c + 1] = d[nt][3];
    }
}

// ---------------- 3) src1/dst1 = Wh1 . alpha ----------------
__global__ void k_srcdst1(const float* __restrict__ alpha1) {
    int wid = blockIdx.x * 8 + (threadIdx.x >> 5);
    int lane = threadIdx.x & 31;
    int h = wid >> 13;
    int i = wid & (NN - 1);
    const float* a = alpha1 + h * 2 * FH;
    float w0 = g_Wh1[h][i][lane], w1 = g_Wh1[h][i][lane + 32];
    float s = w0 * a[lane] + w1 * a[lane + 32];
    float d = w0 * a[FH + lane] + w1 * a[FH + lane + 32];
#pragma unroll
    for (int o = 16; o; o >>= 1) {
        s += __shfl_xor_sync(0xffffffffu, s, o);
        d += __shfl_xor_sync(0xffffffffu, d, o);
    }
    if (!lane) { g_src1[h][i] = s; g_dst1[h][i] = d; }
}

// ---------------- 4) layer-1 attention: upper-bound max + thresholded accumulate ----------------
__global__ __launch_bounds__(512) void k_att1() {
    int h = blockIdx.x >> 7;
    int bx = blockIdx.x & 127;
    int warp = threadIdx.x >> 5, lane = threadIdx.x & 31;
    int row0 = bx * 64 + warp * 4;
    __shared__ float2 sp[64][34];
    __shared__ float sdst[64];
    __shared__ float sred[16];

    // block-wide unmasked dst max (upper bound on any row's masked max)
    float lm = -3e38f;
    for (int i = threadIdx.x; i < NN; i += 512) lm = fmaxf(lm, g_dst1[h][i]);
#pragma unroll
    for (int o = 16; o; o >>= 1) lm = fmaxf(lm, __shfl_xor_sync(0xffffffffu, lm, o));
    if (!lane) sred[warp] = lm;
    __syncthreads();
    if (threadIdx.x == 0) {
        float m = sred[0];
#pragma unroll
        for (int i = 1; i < 16; i++) m = fmaxf(m, sred[i]);
        sred[0] = m;
    }
    __syncthreads();
    float Dmax = sred[0];

    float src[4], mub[4], thr[4], ssum[4];
    float2 acc[4];
#pragma unroll
    for (int r = 0; r < 4; r++) {
        src[r] = g_src1[h][row0 + r];
        float v = src[r] + Dmax;
        mub[r] = fmaxf(v, 0.2f * v);
        thr[r] = mub[r] - THRESH;
        ssum[r] = 0.f; acc[r] = make_float2(0.f, 0.f);
    }
    const float* V = &g_Wh1[h][0][0];
    const unsigned* mk[4];
#pragma unroll
    for (int r = 0; r < 4; r++) mk[r] = g_mask[row0 + r];

    for (int t = 0; t < NN; t += 64) {
#pragma unroll
        for (int i = 0; i < 2; i++) {
            int q = threadIdx.x + i * 512;
            int jj = q >> 4; int c = (q & 15) * 4;
            float4 v4 = *(const float4*)&V[(size_t)(t + jj) * FH + c];
            sp[jj][c >> 1]       = make_float2(v4.x, v4.y);
            sp[jj][(c >> 1) + 1] = make_float2(v4.z, v4.w);
        }
        if (threadIdx.x < 64) sdst[threadIdx.x] = g_dst1[h][t + threadIdx.x];
        __syncthreads();
#pragma unroll
        for (int sub = 0; sub < 2; sub++) {
            float dv = sdst[sub * 32 + lane];
            int wi = (t >> 5) + sub;
#pragma unroll
            for (int r = 0; r < 4; r++) {
                unsigned w = mk[r][wi];
                float v = src[r] + dv;
                float e = fmaxf(v, 0.2f * v);
                float p = 0.0f;
                if (((w >> lane) & 1) && (e > thr[r])) p = __expf(e - mub[r]);
                ssum[r] += p;
                unsigned ball = __ballot_sync(0xffffffffu, p > 0.0f);
                while (ball) {
                    int L = __ffs(ball) - 1; ball &= ball - 1;
                    float pb = __shfl_sync(0xffffffffu, p, L);
                    float2 vv = sp[sub * 32 + L][lane];
                    acc[r].x += pb * vv.x;
                    acc[r].y += pb * vv.y;
                }
            }
        }
        __syncthreads();
    }
#pragma unroll
    for (int r = 0; r < 4; r++) {
        float s = ssum[r];
#pragma unroll
        for (int o = 16; o; o >>= 1) s += __shfl_xor_sync(0xffffffffu, s, o);
        float inv = 1.0f / s;
        float ox = acc[r].x * inv, oy = acc[r].y * inv;
        ox = ox > 0.f ? ox : expm1f(ox);
        oy = oy > 0.f ? oy : expm1f(oy);
        int row = row0 + r;
        g_h1[row][h * FH + 2 * lane]     = ox;
        g_h1[row][h * FH + 2 * lane + 1] = oy;
    }
}

// ---------------- 5) Wh2 = h1 @ W2 (+ src2/dst2) ----------------
__global__ __launch_bounds__(256) void k_gemm2(const float* __restrict__ W2,
                                               const float* __restrict__ alpha2) {
    __shared__ float sW[256][21];
    __shared__ float sa[40];
    int tid = threadIdx.x;
    for (int q = tid; q < 256 * NCLS; q += 256) sW[q / NCLS][q % NCLS] = W2[q];
    if (tid < 40) sa[tid] = alpha2[tid];
    __syncthreads();
    int lane = tid & 31, warp = tid >> 5;
    int row = blockIdx.x * 8 + warp;
    float acc[NCLS];
#pragma unroll
    for (int c = 0; c < NCLS; c++) acc[c] = 0.f;
    for (int k = lane; k < 256; k += 32) {
        float hv = g_h1[row][k];
#pragma unroll
        for (int c = 0; c < NCLS; c++) acc[c] += hv * sW[k][c];
    }
#pragma unroll
    for (int c = 0; c < NCLS; c++)
#pragma unroll
        for (int o = 16; o; o >>= 1) acc[c] += __shfl_xor_sync(0xffffffffu, acc[c], o);
    if (lane == 0) {
        float s = 0.f, d = 0.f;
#pragma unroll
        for (int c = 0; c < NCLS; c++) {
            g_Wh2[row][c] = acc[c];
            s += acc[c] * sa[c];
            d += acc[c] * sa[NCLS + c];
        }
        g_src2[row] = s; g_dst2[row] = d;
    }
}

// ---------------- 6) layer-2 attention -> out ----------------
__global__ __launch_bounds__(256) void k_att2(float* __restrict__ out) {
    int warp = threadIdx.x >> 5, lane = threadIdx.x & 31;
    int row0 = blockIdx.x * 32 + warp * 4;
    __shared__ float sv[64][32];
    __shared__ float sdst2[64];
    __shared__ float sred[8];

    float lm = -3e38f;
    for (int i = threadIdx.x; i < NN; i += 256) lm = fmaxf(lm, g_dst2[i]);
#pragma unroll
    for (int o = 16; o; o >>= 1) lm = fmaxf(lm, __shfl_xor_sync(0xffffffffu, lm, o));
    if (!lane) sred[warp] = lm;
    __syncthreads();
    if (threadIdx.x == 0) {
        float m = sred[0];
#pragma unroll
        for (int i = 1; i < 8; i++) m = fmaxf(m, sred[i]);
        sred[0] = m;
    }
    __syncthreads();
    float Dmax = sred[0];

    float src[4], mub[4], thr[4], accv[4], ssum[4];
#pragma unroll
    for (int r = 0; r < 4; r++) {
        src[r] = g_src2[row0 + r];
        float v = src[r] + Dmax;
        mub[r] = fmaxf(v, 0.2f * v);
        thr[r] = mub[r] - THRESH;
        accv[r] = 0.f; ssum[r] = 0.f;
    }
    const unsigned* mk[4];
#pragma unroll
    for (int r = 0; r < 4; r++) mk[r] = g_mask[row0 + r];

    for (int t = 0; t < NN; t += 64) {
#pragma unroll
        for (int i = 0; i < 5; i++) {
            int q = threadIdx.x + i * 256;
            int jj = q / NCLS; int c = q - jj * NCLS;
            sv[jj][c] = g_Wh2[t + jj][c];
        }
        if (threadIdx.x < 64) sdst2[threadIdx.x] = g_dst2[t + threadIdx.x];
        __syncthreads();
#pragma unroll
        for (int sub = 0; sub < 2; sub++) {
            float dv = sdst2[sub * 32 + lane];
            int wi = (t >> 5) + sub;
#pragma unroll
            for (int r = 0; r < 4; r++) {
                unsigned w = mk[r][wi];
                float v = src[r] + dv;
                float e = fmaxf(v, 0.2f * v);
                float p = 0.0f;
                if (((w >> lane) & 1) && (e > thr[r])) p = __expf(e - mub[r]);
                ssum[r] += p;
                unsigned ball = __ballot_sync(0xffffffffu, p > 0.0f);
                while (ball) {
                    int L = __ffs(ball) - 1; ball &= ball - 1;
                    float pb = __shfl_sync(0xffffffffu, p, L);
                    accv[r] += pb * sv[sub * 32 + L][lane];
                }
            }
        }
        __syncthreads();
    }
#pragma unroll
    for (int r = 0; r < 4; r++) {
        float s = ssum[r];
#pragma unroll
        for (int o = 16; o; o >>= 1) s += __shfl_xor_sync(0xffffffffu, s, o);
        if (lane < NCLS) {
            float o0 = accv[r] / s;
            o0 = o0 > 0.f ? o0 : expm1f(o0);
            out[(size_t)(row0 + r) * NCLS + lane] = o0;
        }
    }
}

// ---------------- launch ----------------
extern "C" void kernel_launch(void* const* d_in, const int* in_sizes, int n_in,
                              void* d_out, int out_size) {
    const float* x      = (const float*)d_in[0];
    const int*   adj    = (const int*)d_in[1];
    const float* W1     = (const float*)d_in[2];
    const float* alpha1 = (const float*)d_in[3];
    const float* W2     = (const float*)d_in[4];
    const float* alpha2 = (const float*)d_in[5];
    float* out = (float*)d_out;

    k_mask<<<(NN * (NN / 32)) / 8, 256>>>(adj);
    k_gemm1<<<dim3(NN / 128, NHEAD), 256>>>(x, W1);
    k_srcdst1<<<NHEAD * NN / 8, 256>>>(alpha1);
    k_att1<<<128 * NHEAD, 512>>>();
    k_gemm2<<<NN / 8, 256>>>(W2, alpha2);
    k_att2<<<NN / 32, 256>>>(out);
}

// round 4
// speedup vs baseline: 2.2381x; 1.7742x over previous
#include <cuda_runtime.h>
#include <cstdint>
#include <cstddef>

#define NN 8192
#define FIN 512
#define FH 64
#define NHEAD 4
#define NCLS 20
#define NPAD2 24
#define LOG2E 1.4426950408889634f

// ---------------- scratch (device globals; no allocations) ----------------
__device__ float g_Wh1[NHEAD][NN][FH];        // 8 MB
__device__ float g_src1[NHEAD][NN];
__device__ float g_dst1[NHEAD][NN];
__device__ float g_h1[NN][NHEAD * FH];        // 8 MB
__device__ unsigned g_mask[NN][NN / 32];      // 8 MB bitmask
__device__ float g_Wh2[NN][NCLS];
__device__ float g_src2[NN];
__device__ float g_dst2[NN];
__device__ float g_dmax1[NHEAD];
__device__ float g_dmax2[1];
// V pre-split into tf32 hi/lo, fragment-friendly layout [k8][split][n][kk][pair]
__device__ float gV1[NHEAD][NN / 8][2][FH][4][2];    // 16 MB
__device__ float gV2[NN / 8][2][NPAD2][4][2];        // 1.5 MB

// ---------------- helpers ----------------
__device__ __forceinline__ uint32_t f2tf32(float f) {
    uint32_t u;
    asm("cvt.rna.tf32.f32 %0, %1;" : "=r"(u) : "f"(f));
    return u;
}
__device__ __forceinline__ void tf32_split(float f, uint32_t& hi, uint32_t& lo) {
    hi = f2tf32(f);
    float r = f - __uint_as_float(hi);
    lo = f2tf32(r);
}
__device__ __forceinline__ void mma_tf32(float* d, const uint32_t* a, const uint32_t* b) {
    asm volatile(
        "mma.sync.aligned.m16n8k8.row.col.f32.tf32.tf32.f32 "
        "{%0,%1,%2,%3},{%4,%5,%6,%7},{%8,%9},{%0,%1,%2,%3};"
        : "+f"(d[0]), "+f"(d[1]), "+f"(d[2]), "+f"(d[3])
        : "r"(a[0]), "r"(a[1]), "r"(a[2]), "r"(a[3]), "r"(b[0]), "r"(b[1]));
}
__device__ __forceinline__ float ex2f(float x) {
    float r;
    asm("ex2.approx.ftz.f32 %0, %1;" : "=f"(r) : "f"(x));
    return r;
}
__device__ __forceinline__ float eluf(float x) { return x > 0.f ? x : expm1f(x); }

// ---------------- 1) adjacency -> bitmask ----------------
__global__ void k_mask(const int* __restrict__ adj) {
    int word = blockIdx.x * 8 + (threadIdx.x >> 5);
    int lane = threadIdx.x & 31;
    size_t idx = (size_t)word * 32 + lane;
    int a = adj[idx];
    unsigned b = __ballot_sync(0xffffffffu, a > 0);
    if (lane == 0) ((unsigned*)g_mask)[word] = b;
}

// ---------------- 2) Wh1[h] = x @ W1[h] via tf32x2 mma ----------------
__global__ __launch_bounds__(256) void k_gemm1(const float* __restrict__ x,
                                               const float* __restrict__ W1) {
    const int h = blockIdx.y;
    const int m0 = blockIdx.x * 128;
    __shared__ float As[128][36];
    __shared__ float Bs[32][68];
    const float* W = W1 + (size_t)h * FIN * FH;
    int tid = threadIdx.x, lane = tid & 31, warp = tid >> 5;
    int l4 = lane >> 2, lm4 = lane & 3;
    int wm = warp * 16;

    float d[8][4];
#pragma unroll
    for (int nt = 0; nt < 8; nt++)
#pragma unroll
        for (int i = 0; i < 4; i++) d[nt][i] = 0.f;

    for (int k0 = 0; k0 < FIN; k0 += 32) {
#pragma unroll
        for (int i = 0; i < 4; i++) {
            int idx = tid + i * 256;
            int row = idx >> 3, c = (idx & 7) * 4;
            float4 v = *(const float4*)&x[(size_t)(m0 + row) * FIN + k0 + c];
            *(float4*)&As[row][c] = v;
        }
#pragma unroll
        for (int i = 0; i < 2; i++) {
            int idx = tid + i * 256;
            int row = idx >> 4, c = (idx & 15) * 4;
            float4 v = *(const float4*)&W[(size_t)(k0 + row) * FH + c];
            *(float4*)&Bs[row][c] = v;
        }
        __syncthreads();
#pragma unroll
        for (int kk = 0; kk < 32; kk += 8) {
            float af[4];
            af[0] = As[wm + l4][kk + lm4];
            af[1] = As[wm + l4 + 8][kk + lm4];
            af[2] = As[wm + l4][kk + lm4 + 4];
            af[3] = As[wm + l4 + 8][kk + lm4 + 4];
            uint32_t ahi[4], alo[4];
#pragma unroll
            for (int i = 0; i < 4; i++) tf32_split(af[i], ahi[i], alo[i]);
#pragma unroll
            for (int nt = 0; nt < 8; nt++) {
                float bf[2];
                bf[0] = Bs[kk + lm4][nt * 8 + l4];
                bf[1] = Bs[kk + lm4 + 4][nt * 8 + l4];
                uint32_t bhi[2], blo[2];
                tf32_split(bf[0], bhi[0], blo[0]);
                tf32_split(bf[1], bhi[1], blo[1]);
                mma_tf32(d[nt], ahi, bhi);
                mma_tf32(d[nt], alo, bhi);
                mma_tf32(d[nt], ahi, blo);
            }
        }
        __syncthreads();
    }
#pragma unroll
    for (int nt = 0; nt < 8; nt++) {
        int r0 = m0 + wm + l4, c = nt * 8 + 2 * lm4;
        g_Wh1[h][r0][c]     = d[nt][0];
        g_Wh1[h][r0][c + 1] = d[nt][1];
        g_Wh1[h][r0 + 8][c]     = d[nt][2];
        g_Wh1[h][r0 + 8][c + 1] = d[nt][3];
    }
}

// ---------------- 3) src1/dst1 = Wh1 . alpha ----------------
__global__ void k_srcdst1(const float* __restrict__ alpha1) {
    int wid = blockIdx.x * 8 + (threadIdx.x >> 5);
    int lane = threadIdx.x & 31;
    int h = wid >> 13;
    int i = wid & (NN - 1);
    const float* a = alpha1 + h * 2 * FH;
    float w0 = g_Wh1[h][i][lane], w1 = g_Wh1[h][i][lane + 32];
    float s = w0 * a[lane] + w1 * a[lane + 32];
    float d = w0 * a[FH + lane] + w1 * a[FH + lane + 32];
#pragma unroll
    for (int o = 16; o; o >>= 1) {
        s += __shfl_xor_sync(0xffffffffu, s, o);
        d += __shfl_xor_sync(0xffffffffu, d, o);
    }
    if (!lane) { g_src1[h][i] = s; g_dst1[h][i] = d; }
}

// ---------------- 4) per-head global dst max ----------------
__global__ void k_dmax1() {
    int h = blockIdx.x;
    __shared__ float sr[8];
    int lane = threadIdx.x & 31, warp = threadIdx.x >> 5;
    float m = -3e38f;
    for (int i = threadIdx.x; i < NN; i += 256) m = fmaxf(m, g_dst1[h][i]);
#pragma unroll
    for (int o = 16; o; o >>= 1) m = fmaxf(m, __shfl_xor_sync(0xffffffffu, m, o));
    if (!lane) sr[warp] = m;
    __syncthreads();
    if (threadIdx.x == 0) {
        float mm = sr[0];
#pragma unroll
        for (int i = 1; i < 8; i++) mm = fmaxf(mm, sr[i]);
        g_dmax1[h] = mm;
    }
}

// ---------------- 5) pre-split V1 into tf32 hi/lo fragment layout ----------------
__global__ __launch_bounds__(256) void k_vprep1() {
    int idx = blockIdx.x * 256 + threadIdx.x;      // 4*1024*4*64 = 1M threads
    int n = idx & 63;
    int kk = (idx >> 6) & 3;
    int k8 = (idx >> 8) & 1023;
    int h = idx >> 18;
    float v0 = g_Wh1[h][k8 * 8 + kk][n];
    float v1 = g_Wh1[h][k8 * 8 + kk + 4][n];
    uint32_t h0, l0, h1, l1;
    tf32_split(v0, h0, l0);
    tf32_split(v1, h1, l1);
    *(float2*)&gV1[h][k8][0][n][kk][0] = make_float2(__uint_as_float(h0), __uint_as_float(h1));
    *(float2*)&gV1[h][k8][1][n][kk][0] = make_float2(__uint_as_float(l0), __uint_as_float(l1));
}

// ---------------- 6) layer-1 dense tensor-core attention ----------------
__global__ __launch_bounds__(256) void k_att1() {
    const int h = blockIdx.y;
    const int tid = threadIdx.x, lane = tid & 31, warp = tid >> 5;
    const int wr0 = blockIdx.x * 256 + warp * 32;
    const int l4 = lane >> 2, lm = lane & 3;
    __shared__ float sV[8][2][FH][4][2];   // 32 KB
    __shared__ float2 sb[64];

    const float Dmax = g_dmax1[h];
    float a1[4], a2[4];
    int rows[4];
#pragma unroll
    for (int f = 0; f < 4; f++) {
        int r = wr0 + l4 + f * 8;
        rows[f] = r;
        float s = g_src1[h][r];
        float v = s + Dmax;
        float mub = fmaxf(v, 0.2f * v);
        a1[f] = (s - mub) * LOG2E;
        a2[f] = (0.2f * s - mub) * LOG2E;
    }

    float d[2][8][4];
#pragma unroll
    for (int fr = 0; fr < 2; fr++)
#pragma unroll
        for (int nt = 0; nt < 8; nt++)
#pragma unroll
            for (int i = 0; i < 4; i++) d[fr][nt][i] = 0.f;
    float srow[4] = {0.f, 0.f, 0.f, 0.f};
    unsigned wmask[4];

    for (int kb = 0; kb < NN / 64; kb++) {
        const float4* src4 = (const float4*)&gV1[h][kb * 8][0][0][0][0];
        float4* dst4 = (float4*)&sV[0][0][0][0][0];
#pragma unroll
        for (int i = 0; i < 8; i++) dst4[tid + i * 256] = src4[tid + i * 256];
        if (tid < 64) {
            float dv = g_dst1[h][kb * 64 + tid];
            sb[tid] = make_float2(dv * LOG2E, 0.2f * LOG2E * dv);
        }
        __syncthreads();
#pragma unroll
        for (int ch = 0; ch < 8; ch++) {
            if ((ch & 3) == 0) {
                int widx = kb * 2 + (ch >> 2);
#pragma unroll
                for (int f = 0; f < 4; f++) wmask[f] = g_mask[rows[f]][widx];
            }
            float2 bc1 = sb[ch * 8 + lm];
            float2 bc2 = sb[ch * 8 + lm + 4];
            int sh = (ch & 3) * 8 + lm;
            float pf[2][4];
#pragma unroll
            for (int f = 0; f < 4; f++) {
                unsigned wv = wmask[f] >> sh;
                float e1 = ex2f(fmaxf(a1[f] + bc1.x, a2[f] + bc1.y));
                float e2 = ex2f(fmaxf(a1[f] + bc2.x, a2[f] + bc2.y));
                unsigned m1 = 0u - (wv & 1u);
                unsigned m2 = 0u - ((wv >> 4) & 1u);
                float p1 = __uint_as_float(__float_as_uint(e1) & m1);
                float p2 = __uint_as_float(__float_as_uint(e2) & m2);
                srow[f] += p1 + p2;
                pf[f >> 1][f & 1] = p1;
                pf[f >> 1][2 + (f & 1)] = p2;
            }
            uint32_t ahi[2][4], alo[2][4];
#pragma unroll
            for (int fr = 0; fr < 2; fr++)
#pragma unroll
                for (int i = 0; i < 4; i++) tf32_split(pf[fr][i], ahi[fr][i], alo[fr][i]);
            const float* sVh = &sV[ch][0][0][0][0];
            const float* sVl = &sV[ch][1][0][0][0];
#pragma unroll
            for (int nt = 0; nt < 8; nt++) {
                int off = ((nt * 8 + l4) * 4 + lm) * 2;
                float2 vh = *(const float2*)&sVh[off];
                float2 vl = *(const float2*)&sVl[off];
                uint32_t bh[2] = {__float_as_uint(vh.x), __float_as_uint(vh.y)};
                uint32_t bl[2] = {__float_as_uint(vl.x), __float_as_uint(vl.y)};
                mma_tf32(d[0][nt], ahi[0], bh);
                mma_tf32(d[0][nt], alo[0], bh);
                mma_tf32(d[0][nt], ahi[0], bl);
                mma_tf32(d[1][nt], ahi[1], bh);
                mma_tf32(d[1][nt], alo[1], bh);
                mma_tf32(d[1][nt], ahi[1], bl);
            }
        }
        __syncthreads();
    }
#pragma unroll
    for (int f = 0; f < 4; f++) {
        srow[f] += __shfl_xor_sync(0xffffffffu, srow[f], 1);
        srow[f] += __shfl_xor_sync(0xffffffffu, srow[f], 2);
        srow[f] = 1.0f / srow[f];
    }
#pragma unroll
    for (int fr = 0; fr < 2; fr++) {
        int r0 = wr0 + l4 + fr * 16;
#pragma unroll
        for (int nt = 0; nt < 8; nt++) {
            int col = h * FH + nt * 8 + lm * 2;
            float x0 = eluf(d[fr][nt][0] * srow[fr * 2]);
            float x1 = eluf(d[fr][nt][1] * srow[fr * 2]);
            float y0 = eluf(d[fr][nt][2] * srow[fr * 2 + 1]);
            float y1 = eluf(d[fr][nt][3] * srow[fr * 2 + 1]);
            *(float2*)&g_h1[r0][col] = make_float2(x0, x1);
            *(float2*)&g_h1[r0 + 8][col] = make_float2(y0, y1);
        }
    }
}

// ---------------- 7) Wh2 = h1 @ W2 (+ src2/dst2) ----------------
__global__ __launch_bounds__(256) void k_gemm2(const float* __restrict__ W2,
                                               const float* __restrict__ alpha2) {
    __shared__ float sW[256][21];
    __shared__ float sa[40];
    int tid = threadIdx.x;
    for (int q = tid; q < 256 * NCLS; q += 256) sW[q / NCLS][q % NCLS] = W2[q];
    if (tid < 40) sa[tid] = alpha2[tid];
    __syncthreads();
    int lane = tid & 31, warp = tid >> 5;
    int row = blockIdx.x * 8 + warp;
    float acc[NCLS];
#pragma unroll
    for (int c = 0; c < NCLS; c++) acc[c] = 0.f;
    for (int k = lane; k < 256; k += 32) {
        float hv = g_h1[row][k];
#pragma unroll
        for (int c = 0; c < NCLS; c++) acc[c] += hv * sW[k][c];
    }
#pragma unroll
    for (int c = 0; c < NCLS; c++)
#pragma unroll
        for (int o = 16; o; o >>= 1) acc[c] += __shfl_xor_sync(0xffffffffu, acc[c], o);
    if (lane == 0) {
        float s = 0.f, d = 0.f;
#pragma unroll
        for (int c = 0; c < NCLS; c++) {
            g_Wh2[row][c] = acc[c];
            s += acc[c] * sa[c];
            d += acc[c] * sa[NCLS + c];
        }
        g_src2[row] = s; g_dst2[row] = d;
    }
}

// ---------------- 8) layer-2 dst max ----------------
__global__ void k_dmax2() {
    __shared__ float sr[8];
    int lane = threadIdx.x & 31, warp = threadIdx.x >> 5;
    float m = -3e38f;
    for (int i = threadIdx.x; i < NN; i += 256) m = fmaxf(m, g_dst2[i]);
#pragma unroll
    for (int o = 16; o; o >>= 1) m = fmaxf(m, __shfl_xor_sync(0xffffffffu, m, o));
    if (!lane) sr[warp] = m;
    __syncthreads();
    if (threadIdx.x == 0) {
        float mm = sr[0];
#pragma unroll
        for (int i = 1; i < 8; i++) mm = fmaxf(mm, sr[i]);
        g_dmax2[0] = mm;
    }
}

// ---------------- 9) pre-split V2 (padded to 24 cols) ----------------
__global__ __launch_bounds__(256) void k_vprep2() {
    int idx = blockIdx.x * 256 + threadIdx.x;     // 1024*4*24 = 98304 threads
    int n = idx % NPAD2;
    int kk = (idx / NPAD2) & 3;
    int k8 = idx / (NPAD2 * 4);
    float v0 = (n < NCLS) ? g_Wh2[k8 * 8 + kk][n] : 0.f;
    float v1 = (n < NCLS) ? g_Wh2[k8 * 8 + kk + 4][n] : 0.f;
    uint32_t h0, l0, h1, l1;
    tf32_split(v0, h0, l0);
    tf32_split(v1, h1, l1);
    *(float2*)&gV2[k8][0][n][kk][0] = make_float2(__uint_as_float(h0), __uint_as_float(h1));
    *(float2*)&gV2[k8][1][n][kk][0] = make_float2(__uint_as_float(l0), __uint_as_float(l1));
}

// ---------------- 10) layer-2 dense tensor-core attention -> out ----------------
__global__ __launch_bounds__(64) void k_att2(float* __restrict__ out) {
    const int tid = threadIdx.x, lane = tid & 31, warp = tid >> 5;
    const int wr0 = blockIdx.x * 64 + warp * 32;
    const int l4 = lane >> 2, lm = lane & 3;
    __shared__ float sV[8][2][NPAD2][4][2];   // 12 KB
    __shared__ float2 sb[64];

    const float Dmax = g_dmax2[0];
    float a1[4], a2[4];
    int rows[4];
#pragma unroll
    for (int f = 0; f < 4; f++) {
        int r = wr0 + l4 + f * 8;
        rows[f] = r;
        float s = g_src2[r];
        float v = s + Dmax;
        float mub = fmaxf(v, 0.2f * v);
        a1[f] = (s - mub) * LOG2E;
        a2[f] = (0.2f * s - mub) * LOG2E;
    }

    float d[2][3][4];
#pragma unroll
    for (int fr = 0; fr < 2; fr++)
#pragma unroll
        for (int nt = 0; nt < 3; nt++)
#pragma unroll
            for (int i = 0; i < 4; i++) d[fr][nt][i] = 0.f;
    float srow[4] = {0.f, 0.f, 0.f, 0.f};
    unsigned wmask[4];

    for (int kb = 0; kb < NN / 64; kb++) {
        const float4* src4 = (const float4*)&gV2[kb * 8][0][0][0][0];
        float4* dst4 = (float4*)&sV[0][0][0][0][0];
#pragma unroll
        for (int i = 0; i < 12; i++) dst4[tid + i * 64] = src4[tid + i * 64];
        {
            float dv = g_dst2[kb * 64 + tid];
            sb[tid] = make_float2(dv * LOG2E, 0.2f * LOG2E * dv);
        }
        __syncthreads();
#pragma unroll
        for (int ch = 0; ch < 8; ch++) {
            if ((ch & 3) == 0) {
                int widx = kb * 2 + (ch >> 2);
#pragma unroll
                for (int f = 0; f < 4; f++) wmask[f] = g_mask[rows[f]][widx];
            }
            float2 bc1 = sb[ch * 8 + lm];
            float2 bc2 = sb[ch * 8 + lm + 4];
            int sh = (ch & 3) * 8 + lm;
            float pf[2][4];
#pragma unroll
            for (int f = 0; f < 4; f++) {
                unsigned wv = wmask[f] >> sh;
                float e1 = ex2f(fmaxf(a1[f] + bc1.x, a2[f] + bc1.y));
                float e2 = ex2f(fmaxf(a1[f] + bc2.x, a2[f] + bc2.y));
                unsigned m1 = 0u - (wv & 1u);
                unsigned m2 = 0u - ((wv >> 4) & 1u);
                float p1 = __uint_as_float(__float_as_uint(e1) & m1);
                float p2 = __uint_as_float(__float_as_uint(e2) & m2);
                srow[f] += p1 + p2;
                pf[f >> 1][f & 1] = p1;
                pf[f >> 1][2 + (f & 1)] = p2;
            }
            uint32_t ahi[2][4], alo[2][4];
#pragma unroll
            for (int fr = 0; fr < 2; fr++)
#pragma unroll
                for (int i = 0; i < 4; i++) tf32_split(pf[fr][i], ahi[fr][i], alo[fr][i]);
            const float* sVh = &sV[ch][0][0][0][0];
            const float* sVl = &sV[ch][1][0][0][0];
#pragma unroll
            for (int nt = 0; nt < 3; nt++) {
                int off = ((nt * 8 + l4) * 4 + lm) * 2;
                float2 vh = *(const float2*)&sVh[off];
                float2 vl = *(const float2*)&sVl[off];
                uint32_t bh[2] = {__float_as_uint(vh.x), __float_as_uint(vh.y)};
                uint32_t bl[2] = {__float_as_uint(vl.x), __float_as_uint(vl.y)};
                mma_tf32(d[0][nt], ahi[0], bh);
                mma_tf32(d[0][nt], alo[0], bh);
                mma_tf32(d[0][nt], ahi[0], bl);
                mma_tf32(d[1][nt], ahi[1], bh);
                mma_tf32(d[1][nt], alo[1], bh);
                mma_tf32(d[1][nt], ahi[1], bl);
            }
        }
        __syncthreads();
    }
#pragma unroll
    for (int f = 0; f < 4; f++) {
        srow[f] += __shfl_xor_sync(0xffffffffu, srow[f], 1);
        srow[f] += __shfl_xor_sync(0xffffffffu, srow[f], 2);
        srow[f] = 1.0f / srow[f];
    }
#pragma unroll
    for (int fr = 0; fr < 2; fr++) {
        int r0 = wr0 + l4 + fr * 16;
#pragma unroll
        for (int nt = 0; nt < 3; nt++) {
            int col = nt * 8 + lm * 2;
            if (col < NCLS) {
                float x0 = eluf(d[fr][nt][0] * srow[fr * 2]);
                float x1 = eluf(d[fr][nt][1] * srow[fr * 2]);
                float y0 = eluf(d[fr][nt][2] * srow[fr * 2 + 1]);
                float y1 = eluf(d[fr][nt][3] * srow[fr * 2 + 1]);
                *(float2*)&out[(size_t)r0 * NCLS + col] = make_float2(x0, x1);
                *(float2*)&out[(size_t)(r0 + 8) * NCLS + col] = make_float2(y0, y1);
            }
        }
    }
}

// ---------------- launch ----------------
extern "C" void kernel_launch(void* const* d_in, const int* in_sizes, int n_in,
                              void* d_out, int out_size) {
    const float* x      = (const float*)d_in[0];
    const int*   adj    = (const int*)d_in[1];
    const float* W1     = (const float*)d_in[2];
    const float* alpha1 = (const float*)d_in[3];
    const float* W2     = (const float*)d_in[4];
    const float* alpha2 = (const float*)d_in[5];
    float* out = (float*)d_out;

    k_mask<<<(NN * (NN / 32)) / 8, 256>>>(adj);
    k_gemm1<<<dim3(NN / 128, NHEAD), 256>>>(x, W1);
    k_srcdst1<<<NHEAD * NN / 8, 256>>>(alpha1);
    k_dmax1<<<NHEAD, 256>>>();
    k_vprep1<<<(NHEAD * (NN / 8) * 4 * FH) / 256, 256>>>();
    k_att1<<<dim3(NN / 256, NHEAD), 256>>>();
    k_gemm2<<<NN / 8, 256>>>(W2, alpha2);
    k_dmax2<<<1, 256>>>();
    k_vprep2<<<((NN / 8) * 4 * NPAD2) / 256, 256>>>();
    k_att2<<<NN / 64, 64>>>(out);
}

// round 5
// speedup vs baseline: 3.4191x; 1.5277x over previous
#include <cuda_runtime.h>
#include <cstdint>
#include <cstddef>

#define NN 8192
#define FIN 512
#define FH 64
#define NHEAD 4
#define NCLS 20
#define NPAD2 24
#define LOG2E 1.4426950408889634f

// ---------------- scratch (device globals; no allocations) ----------------
__device__ float g_Wh1[NHEAD][NN][FH];        // 8 MB
__device__ float g_src1[NHEAD][NN];
__device__ float g_dst1[NHEAD][NN];
__device__ float g_h1[NN][NHEAD * FH];        // 8 MB
__device__ unsigned g_mask[NN][NN / 32];      // 8 MB bitmask
__device__ float g_Wh2[NN][NCLS];
__device__ float g_src2[NN];
__device__ float g_dst2[NN];
__device__ float g_dmax1[NHEAD];
__device__ float g_dmax2[1];
// V pre-rounded to tf32, fragment-friendly layout [k8][n][kk][pair]
__device__ float gV1[NHEAD][NN / 8][FH][4][2];    // 8 MB
__device__ float gV2[NN / 8][NPAD2][4][2];        // 768 KB

// ---------------- helpers ----------------
__device__ __forceinline__ uint32_t f2tf32(float f) {
    uint32_t u;
    asm("cvt.rna.tf32.f32 %0, %1;" : "=r"(u) : "f"(f));
    return u;
}
__device__ __forceinline__ void tf32_split(float f, uint32_t& hi, uint32_t& lo) {
    hi = f2tf32(f);
    float r = f - __uint_as_float(hi);
    lo = f2tf32(r);
}
__device__ __forceinline__ void mma_tf32(float* d, const uint32_t* a, const uint32_t* b) {
    asm volatile(
        "mma.sync.aligned.m16n8k8.row.col.f32.tf32.tf32.f32 "
        "{%0,%1,%2,%3},{%4,%5,%6,%7},{%8,%9},{%0,%1,%2,%3};"
        : "+f"(d[0]), "+f"(d[1]), "+f"(d[2]), "+f"(d[3])
        : "r"(a[0]), "r"(a[1]), "r"(a[2]), "r"(a[3]), "r"(b[0]), "r"(b[1]));
}
__device__ __forceinline__ float ex2f(float x) {
    float r;
    asm("ex2.approx.ftz.f32 %0, %1;" : "=f"(r) : "f"(x));
    return r;
}
__device__ __forceinline__ float eluf(float x) { return x > 0.f ? x : expm1f(x); }

// ---------------- 1) adjacency -> bitmask ----------------
__global__ void k_mask(const int* __restrict__ adj) {
    int word = blockIdx.x * 8 + (threadIdx.x >> 5);
    int lane = threadIdx.x & 31;
    size_t idx = (size_t)word * 32 + lane;
    int a = adj[idx];
    unsigned b = __ballot_sync(0xffffffffu, a > 0);
    if (lane == 0) ((unsigned*)g_mask)[word] = b;
}

// ---------------- 2) Wh1[h] = x @ W1[h] via tf32x2 mma ----------------
__global__ __launch_bounds__(256) void k_gemm1(const float* __restrict__ x,
                                               const float* __restrict__ W1) {
    const int h = blockIdx.y;
    const int m0 = blockIdx.x * 128;
    __shared__ float As[128][36];
    __shared__ float Bs[32][68];
    const float* W = W1 + (size_t)h * FIN * FH;
    int tid = threadIdx.x, lane = tid & 31, warp = tid >> 5;
    int l4 = lane >> 2, lm4 = lane & 3;
    int wm = warp * 16;

    float d[8][4];
#pragma unroll
    for (int nt = 0; nt < 8; nt++)
#pragma unroll
        for (int i = 0; i < 4; i++) d[nt][i] = 0.f;

    for (int k0 = 0; k0 < FIN; k0 += 32) {
#pragma unroll
        for (int i = 0; i < 4; i++) {
            int idx = tid + i * 256;
            int row = idx >> 3, c = (idx & 7) * 4;
            float4 v = *(const float4*)&x[(size_t)(m0 + row) * FIN + k0 + c];
            *(float4*)&As[row][c] = v;
        }
#pragma unroll
        for (int i = 0; i < 2; i++) {
            int idx = tid + i * 256;
            int row = idx >> 4, c = (idx & 15) * 4;
            float4 v = *(const float4*)&W[(size_t)(k0 + row) * FH + c];
            *(float4*)&Bs[row][c] = v;
        }
        __syncthreads();
#pragma unroll
        for (int kk = 0; kk < 32; kk += 8) {
            float af[4];
            af[0] = As[wm + l4][kk + lm4];
            af[1] = As[wm + l4 + 8][kk + lm4];
            af[2] = As[wm + l4][kk + lm4 + 4];
            af[3] = As[wm + l4 + 8][kk + lm4 + 4];
            uint32_t ahi[4], alo[4];
#pragma unroll
            for (int i = 0; i < 4; i++) tf32_split(af[i], ahi[i], alo[i]);
#pragma unroll
            for (int nt = 0; nt < 8; nt++) {
                float bf[2];
                bf[0] = Bs[kk + lm4][nt * 8 + l4];
                bf[1] = Bs[kk + lm4 + 4][nt * 8 + l4];
                uint32_t bhi[2], blo[2];
                tf32_split(bf[0], bhi[0], blo[0]);
                tf32_split(bf[1], bhi[1], blo[1]);
                mma_tf32(d[nt], ahi, bhi);
                mma_tf32(d[nt], alo, bhi);
                mma_tf32(d[nt], ahi, blo);
            }
        }
        __syncthreads();
    }
#pragma unroll
    for (int nt = 0; nt < 8; nt++) {
        int r0 = m0 + wm + l4, c = nt * 8 + 2 * lm4;
        g_Wh1[h][r0][c]     = d[nt][0];
        g_Wh1[h][r0][c + 1] = d[nt][1];
        g_Wh1[h][r0 + 8][c]     = d[nt][2];
        g_Wh1[h][r0 + 8][c + 1] = d[nt][3];
    }
}

// ---------------- 3) src1/dst1 = Wh1 . alpha ----------------
__global__ void k_srcdst1(const float* __restrict__ alpha1) {
    int wid = blockIdx.x * 8 + (threadIdx.x >> 5);
    int lane = threadIdx.x & 31;
    int h = wid >> 13;
    int i = wid & (NN - 1);
    const float* a = alpha1 + h * 2 * FH;
    float w0 = g_Wh1[h][i][lane], w1 = g_Wh1[h][i][lane + 32];
    float s = w0 * a[lane] + w1 * a[lane + 32];
    float d = w0 * a[FH + lane] + w1 * a[FH + lane + 32];
#pragma unroll
    for (int o = 16; o; o >>= 1) {
        s += __shfl_xor_sync(0xffffffffu, s, o);
        d += __shfl_xor_sync(0xffffffffu, d, o);
    }
    if (!lane) { g_src1[h][i] = s; g_dst1[h][i] = d; }
}

// ---------------- 4) per-head global dst max ----------------
__global__ void k_dmax1() {
    int h = blockIdx.x;
    __shared__ float sr[8];
    int lane = threadIdx.x & 31, warp = threadIdx.x >> 5;
    float m = -3e38f;
    for (int i = threadIdx.x; i < NN; i += 256) m = fmaxf(m, g_dst1[h][i]);
#pragma unroll
    for (int o = 16; o; o >>= 1) m = fmaxf(m, __shfl_xor_sync(0xffffffffu, m, o));
    if (!lane) sr[warp] = m;
    __syncthreads();
    if (threadIdx.x == 0) {
        float mm = sr[0];
#pragma unroll
        for (int i = 1; i < 8; i++) mm = fmaxf(mm, sr[i]);
        g_dmax1[h] = mm;
    }
}

// ---------------- 5) V1 -> tf32-rounded fragment layout (hi only) ----------------
__global__ __launch_bounds__(256) void k_vprep1() {
    int idx = blockIdx.x * 256 + threadIdx.x;      // 4*1024*4*64 = 1M threads
    int n = idx & 63;
    int kk = (idx >> 6) & 3;
    int k8 = (idx >> 8) & 1023;
    int h = idx >> 18;
    float v0 = g_Wh1[h][k8 * 8 + kk][n];
    float v1 = g_Wh1[h][k8 * 8 + kk + 4][n];
    *(float2*)&gV1[h][k8][n][kk][0] =
        make_float2(__uint_as_float(f2tf32(v0)), __uint_as_float(f2tf32(v1)));
}

// ---------------- 6) layer-1 dense tensor-core attention ----------------
__global__ __launch_bounds__(128) void k_att1() {
    const int h = blockIdx.y;
    const int tid = threadIdx.x, lane = tid & 31, warp = tid >> 5;
    const int wr0 = blockIdx.x * 128 + warp * 32;
    const int l4 = lane >> 2, lm = lane & 3;
    __shared__ float sV[8][FH][4][2];   // 16 KB
    __shared__ float2 sb[64];

    const float Dmax = g_dmax1[h];
    float a1[4], a2[4];
    int rows[4];
#pragma unroll
    for (int f = 0; f < 4; f++) {
        int r = wr0 + l4 + f * 8;
        rows[f] = r;
        float s = g_src1[h][r];
        float v = s + Dmax;
        float mub = fmaxf(v, 0.2f * v);
        a1[f] = (s - mub) * LOG2E;
        a2[f] = (0.2f * s - mub) * LOG2E;
    }

    float d[2][8][4];
#pragma unroll
    for (int fr = 0; fr < 2; fr++)
#pragma unroll
        for (int nt = 0; nt < 8; nt++)
#pragma unroll
            for (int i = 0; i < 4; i++) d[fr][nt][i] = 0.f;
    float srow[4] = {0.f, 0.f, 0.f, 0.f};
    unsigned wmask[4];

    for (int kb = 0; kb < NN / 64; kb++) {
        const float4* src4 = (const float4*)&gV1[h][kb * 8][0][0][0];
        float4* dst4 = (float4*)&sV[0][0][0][0];
#pragma unroll
        for (int i = 0; i < 8; i++) dst4[tid + i * 128] = src4[tid + i * 128];
        if (tid < 64) {
            float dv = g_dst1[h][kb * 64 + tid];
            sb[tid] = make_float2(dv * LOG2E, 0.2f * LOG2E * dv);
        }
        __syncthreads();
#pragma unroll
        for (int ch = 0; ch < 8; ch++) {
            if ((ch & 3) == 0) {
                int widx = kb * 2 + (ch >> 2);
#pragma unroll
                for (int f = 0; f < 4; f++) wmask[f] = g_mask[rows[f]][widx];
            }
            float2 bc1 = sb[ch * 8 + lm];
            float2 bc2 = sb[ch * 8 + lm + 4];
            int sh = (ch & 3) * 8 + lm;
            float pf[2][4];
#pragma unroll
            for (int f = 0; f < 4; f++) {
                unsigned wv = wmask[f] >> sh;
                float e1 = ex2f(fmaxf(a1[f] + bc1.x, a2[f] + bc1.y));
                float e2 = ex2f(fmaxf(a1[f] + bc2.x, a2[f] + bc2.y));
                unsigned m1 = 0u - (wv & 1u);
                unsigned m2 = 0u - ((wv >> 4) & 1u);
                float p1 = __uint_as_float(__float_as_uint(e1) & m1);
                float p2 = __uint_as_float(__float_as_uint(e2) & m2);
                srow[f] += p1 + p2;
                pf[f >> 1][f & 1] = p1;
                pf[f >> 1][2 + (f & 1)] = p2;
            }
            uint32_t ahi[2][4], alo[2][4];
#pragma unroll
            for (int fr = 0; fr < 2; fr++)
#pragma unroll
                for (int i = 0; i < 4; i++) tf32_split(pf[fr][i], ahi[fr][i], alo[fr][i]);
            const float* sVh = &sV[ch][0][0][0];
#pragma unroll
            for (int nt = 0; nt < 8; nt++) {
                int off = ((nt * 8 + l4) * 4 + lm) * 2;
                float2 vh = *(const float2*)&sVh[off];
                uint32_t bh[2] = {__float_as_uint(vh.x), __float_as_uint(vh.y)};
                mma_tf32(d[0][nt], ahi[0], bh);
                mma_tf32(d[0][nt], alo[0], bh);
                mma_tf32(d[1][nt], ahi[1], bh);
                mma_tf32(d[1][nt], alo[1], bh);
            }
        }
        __syncthreads();
    }
#pragma unroll
    for (int f = 0; f < 4; f++) {
        srow[f] += __shfl_xor_sync(0xffffffffu, srow[f], 1);
        srow[f] += __shfl_xor_sync(0xffffffffu, srow[f], 2);
        srow[f] = 1.0f / srow[f];
    }
#pragma unroll
    for (int fr = 0; fr < 2; fr++) {
        int r0 = wr0 + l4 + fr * 16;
#pragma unroll
        for (int nt = 0; nt < 8; nt++) {
            int col = h * FH + nt * 8 + lm * 2;
            float x0 = eluf(d[fr][nt][0] * srow[fr * 2]);
            float x1 = eluf(d[fr][nt][1] * srow[fr * 2]);
            float y0 = eluf(d[fr][nt][2] * srow[fr * 2 + 1]);
            float y1 = eluf(d[fr][nt][3] * srow[fr * 2 + 1]);
            *(float2*)&g_h1[r0][col] = make_float2(x0, x1);
            *(float2*)&g_h1[r0 + 8][col] = make_float2(y0, y1);
        }
    }
}

// ---------------- 7) Wh2 = h1 @ W2 (+ src2/dst2) ----------------
__global__ __launch_bounds__(256) void k_gemm2(const float* __restrict__ W2,
                                               const float* __restrict__ alpha2) {
    __shared__ float sW[256][21];
    __shared__ float sa[40];
    int tid = threadIdx.x;
    for (int q = tid; q < 256 * NCLS; q += 256) sW[q / NCLS][q % NCLS] = W2[q];
    if (tid < 40) sa[tid] = alpha2[tid];
    __syncthreads();
    int lane = tid & 31, warp = tid >> 5;
    int row = blockIdx.x * 8 + warp;
    float acc[NCLS];
#pragma unroll
    for (int c = 0; c < NCLS; c++) acc[c] = 0.f;
    for (int k = lane; k < 256; k += 32) {
        float hv = g_h1[row][k];
#pragma unroll
        for (int c = 0; c < NCLS; c++) acc[c] += hv * sW[k][c];
    }
#pragma unroll
    for (int c = 0; c < NCLS; c++)
#pragma unroll
        for (int o = 16; o; o >>= 1) acc[c] += __shfl_xor_sync(0xffffffffu, acc[c], o);
    if (lane == 0) {
        float s = 0.f, d = 0.f;
#pragma unroll
        for (int c = 0; c < NCLS; c++) {
            g_Wh2[row][c] = acc[c];
            s += acc[c] * sa[c];
            d += acc[c] * sa[NCLS + c];
        }
        g_src2[row] = s; g_dst2[row] = d;
    }
}

// ---------------- 8) layer-2 dst max ----------------
__global__ void k_dmax2() {
    __shared__ float sr[8];
    int lane = threadIdx.x & 31, warp = threadIdx.x >> 5;
    float m = -3e38f;
    for (int i = threadIdx.x; i < NN; i += 256) m = fmaxf(m, g_dst2[i]);
#pragma unroll
    for (int o = 16; o; o >>= 1) m = fmaxf(m, __shfl_xor_sync(0xffffffffu, m, o));
    if (!lane) sr[warp] = m;
    __syncthreads();
    if (threadIdx.x == 0) {
        float mm = sr[0];
#pragma unroll
        for (int i = 1; i < 8; i++) mm = fmaxf(mm, sr[i]);
        g_dmax2[0] = mm;
    }
}

// ---------------- 9) V2 -> tf32-rounded fragment layout (padded to 24 cols) ----------------
__global__ __launch_bounds__(256) void k_vprep2() {
    int idx = blockIdx.x * 256 + threadIdx.x;     // 1024*4*24 = 98304 threads
    int n = idx % NPAD2;
    int kk = (idx / NPAD2) & 3;
    int k8 = idx / (NPAD2 * 4);
    float v0 = (n < NCLS) ? g_Wh2[k8 * 8 + kk][n] : 0.f;
    float v1 = (n < NCLS) ? g_Wh2[k8 * 8 + kk + 4][n] : 0.f;
    *(float2*)&gV2[k8][n][kk][0] =
        make_float2(__uint_as_float(f2tf32(v0)), __uint_as_float(f2tf32(v1)));
}

// ---------------- 10) layer-2 attention, split-K across 8 warps -> out ----------------
__global__ __launch_bounds__(256) void k_att2(float* __restrict__ out) {
    const int tid = threadIdx.x, lane = tid & 31, warp = tid >> 5;
    const int wr0 = blockIdx.x * 32;
    const int l4 = lane >> 2, lm = lane & 3;
    __shared__ float red[8][32][28];   // 28 KB

    const float Dmax = g_dmax2[0];
    float a1[4], a2[4];
    int rows[4];
#pragma unroll
    for (int f = 0; f < 4; f++) {
        int r = wr0 + l4 + f * 8;
        rows[f] = r;
        float s = g_src2[r];
        float v = s + Dmax;
        float mub = fmaxf(v, 0.2f * v);
        a1[f] = (s - mub) * LOG2E;
        a2[f] = (0.2f * s - mub) * LOG2E;
    }

    float d[2][3][4];
#pragma unroll
    for (int fr = 0; fr < 2; fr++)
#pragma unroll
        for (int nt = 0; nt < 3; nt++)
#pragma unroll
            for (int i = 0; i < 4; i++) d[fr][nt][i] = 0.f;
    float srow[4] = {0.f, 0.f, 0.f, 0.f};
    unsigned wmask[4];

    for (int kb = warp; kb < NN / 64; kb += 8) {
#pragma unroll
        for (int ch = 0; ch < 8; ch++) {
            if ((ch & 3) == 0) {
                int widx = kb * 2 + (ch >> 2);
#pragma unroll
                for (int f = 0; f < 4; f++) wmask[f] = g_mask[rows[f]][widx];
            }
            float dv1 = g_dst2[kb * 64 + ch * 8 + lm];
            float dv2 = g_dst2[kb * 64 + ch * 8 + lm + 4];
            float b1x = dv1 * LOG2E, b1y = 0.2f * LOG2E * dv1;
            float b2x = dv2 * LOG2E, b2y = 0.2f * LOG2E * dv2;
            int sh = (ch & 3) * 8 + lm;
            float pf[2][4];
#pragma unroll
            for (int f = 0; f < 4; f++) {
                unsigned wv = wmask[f] >> sh;
                float e1 = ex2f(fmaxf(a1[f] + b1x, a2[f] + b1y));
                float e2 = ex2f(fmaxf(a1[f] + b2x, a2[f] + b2y));
                unsigned m1 = 0u - (wv & 1u);
                unsigned m2 = 0u - ((wv >> 4) & 1u);
                float p1 = __uint_as_float(__float_as_uint(e1) & m1);
                float p2 = __uint_as_float(__float_as_uint(e2) & m2);
                srow[f] += p1 + p2;
                pf[f >> 1][f & 1] = p1;
                pf[f >> 1][2 + (f & 1)] = p2;
            }
            uint32_t ahi[2][4], alo[2][4];
#pragma unroll
            for (int fr = 0; fr < 2; fr++)
#pragma unroll
                for (int i = 0; i < 4; i++) tf32_split(pf[fr][i], ahi[fr][i], alo[fr][i]);
            const float* Vc = &gV2[kb * 8 + ch][0][0][0];
#pragma unroll
            for (int nt = 0; nt < 3; nt++) {
                float2 vh = *(const float2*)&Vc[((nt * 8 + l4) * 4 + lm) * 2];
                uint32_t bh[2] = {__float_as_uint(vh.x), __float_as_uint(vh.y)};
                mma_tf32(d[0][nt], ahi[0], bh);
                mma_tf32(d[0][nt], alo[0], bh);
                mma_tf32(d[1][nt], ahi[1], bh);
                mma_tf32(d[1][nt], alo[1], bh);
            }
        }
    }
    // cross-warp reduction
#pragma unroll
    for (int fr = 0; fr < 2; fr++)
#pragma unroll
        for (int nt = 0; nt < 3; nt++)
#pragma unroll
            for (int i = 0; i < 4; i++)
                red[warp][lane][(fr * 3 + nt) * 4 + i] = d[fr][nt][i];
#pragma unroll
    for (int f = 0; f < 4; f++) red[warp][lane][24 + f] = srow[f];
    __syncthreads();
    if (warp == 0) {
        float dd[2][3][4], ss[4];
#pragma unroll
        for (int fr = 0; fr < 2; fr++)
#pragma unroll
            for (int nt = 0; nt < 3; nt++)
#pragma unroll
                for (int i = 0; i < 4; i++) {
                    float s = 0.f;
#pragma unroll
                    for (int w = 0; w < 8; w++) s += red[w][lane][(fr * 3 + nt) * 4 + i];
                    dd[fr][nt][i] = s;
                }
#pragma unroll
        for (int f = 0; f < 4; f++) {
            float s = 0.f;
#pragma unroll
            for (int w = 0; w < 8; w++) s += red[w][lane][24 + f];
            s += __shfl_xor_sync(0xffffffffu, s, 1);
            s += __shfl_xor_sync(0xffffffffu, s, 2);
            ss[f] = 1.0f / s;
        }
#pragma unroll
        for (int fr = 0; fr < 2; fr++) {
            int r0 = wr0 + l4 + fr * 16;
#pragma unroll
            for (int nt = 0; nt < 3; nt++) {
                int col = nt * 8 + lm * 2;
                if (col < NCLS) {
                    float x0 = eluf(dd[fr][nt][0] * ss[fr * 2]);
                    float x1 = eluf(dd[fr][nt][1] * ss[fr * 2]);
                    float y0 = eluf(dd[fr][nt][2] * ss[fr * 2 + 1]);
                    float y1 = eluf(dd[fr][nt][3] * ss[fr * 2 + 1]);
                    *(float2*)&out[(size_t)r0 * NCLS + col] = make_float2(x0, x1);
                    *(float2*)&out[(size_t)(r0 + 8) * NCLS + col] = make_float2(y0, y1);
                }
            }
        }
    }
}

// ---------------- launch ----------------
extern "C" void kernel_launch(void* const* d_in, const int* in_sizes, int n_in,
                              void* d_out, int out_size) {
    const float* x      = (const float*)d_in[0];
    const int*   adj    = (const int*)d_in[1];
    const float* W1     = (const float*)d_in[2];
    const float* alpha1 = (const float*)d_in[3];
    const float* W2     = (const float*)d_in[4];
    const float* alpha2 = (const float*)d_in[5];
    float* out = (float*)d_out;

    k_mask<<<(NN * (NN / 32)) / 8, 256>>>(adj);
    k_gemm1<<<dim3(NN / 128, NHEAD), 256>>>(x, W1);
    k_srcdst1<<<NHEAD * NN / 8, 256>>>(alpha1);
    k_dmax1<<<NHEAD, 256>>>();
    k_vprep1<<<(NHEAD * (NN / 8) * 4 * FH) / 256, 256>>>();
    k_att1<<<dim3(NN / 128, NHEAD), 128>>>();
    k_gemm2<<<NN / 8, 256>>>(W2, alpha2);
    k_dmax2<<<1, 256>>>();
    k_vprep2<<<((NN / 8) * 4 * NPAD2) / 256, 256>>>();
    k_att2<<<NN / 32, 256>>>(out);
}

// round 6
// speedup vs baseline: 5.2525x; 1.5362x over previous
#include <cuda_runtime.h>
#include <cstdint>
#include <cstddef>

#define NN 8192
#define FIN 512
#define FH 64
#define NHEAD 4
#define NCLS 20
#define LOG2E 1.4426950408889634f

// ---------------- scratch (device globals; no allocations) ----------------
__device__ float g_Wh1[NHEAD][NN][FH];        // 8 MB
__device__ float g_src1[NHEAD][NN];
__device__ float g_dst1[NHEAD][NN];
__device__ float g_h1[NN][NHEAD * FH];        // 8 MB
__device__ unsigned g_mask[NN][NN / 32];      // 8 MB bitmask
__device__ float g_Wh2[NN][NCLS];
__device__ float g_src2[NN];
__device__ float g_dst2[NN];
__device__ unsigned g_dmax1u[NHEAD];
__device__ unsigned g_dmax2u[1];
// V packed as fp16 half2 in m16n8k16 B-fragment layout: [k16][n][lm][pairsel]
__device__ uint32_t gV1h[NHEAD][NN / 16][FH][4][2];   // 4 MB
__device__ uint32_t gV2h[NN / 16][24][4][2];          // 384 KB

// ---------------- helpers ----------------
__device__ __forceinline__ uint32_t f2tf32(float f) {
    uint32_t u;
    asm("cvt.rna.tf32.f32 %0, %1;" : "=r"(u) : "f"(f));
    return u;
}
__device__ __forceinline__ void tf32_split(float f, uint32_t& hi, uint32_t& lo) {
    hi = f2tf32(f);
    float r = f - __uint_as_float(hi);
    lo = f2tf32(r);
}
__device__ __forceinline__ void mma_tf32(float* d, const uint32_t* a, const uint32_t* b) {
    asm volatile(
        "mma.sync.aligned.m16n8k8.row.col.f32.tf32.tf32.f32 "
        "{%0,%1,%2,%3},{%4,%5,%6,%7},{%8,%9},{%0,%1,%2,%3};"
        : "+f"(d[0]), "+f"(d[1]), "+f"(d[2]), "+f"(d[3])
        : "r"(a[0]), "r"(a[1]), "r"(a[2]), "r"(a[3]), "r"(b[0]), "r"(b[1]));
}
__device__ __forceinline__ void mma_f16(float* d, const uint32_t* a, uint32_t b0, uint32_t b1) {
    asm volatile(
        "mma.sync.aligned.m16n8k16.row.col.f32.f16.f16.f32 "
        "{%0,%1,%2,%3},{%4,%5,%6,%7},{%8,%9},{%0,%1,%2,%3};"
        : "+f"(d[0]), "+f"(d[1]), "+f"(d[2]), "+f"(d[3])
        : "r"(a[0]), "r"(a[1]), "r"(a[2]), "r"(a[3]), "r"(b0), "r"(b1));
}
__device__ __forceinline__ uint32_t packh2(float hi, float lo) {
    uint32_t r;
    asm("cvt.rn.f16x2.f32 %0, %1, %2;" : "=r"(r) : "f"(hi), "f"(lo));
    return r;
}
__device__ __forceinline__ float ex2f(float x) {
    float r;
    asm("ex2.approx.ftz.f32 %0, %1;" : "=f"(r) : "f"(x));
    return r;
}
__device__ __forceinline__ float eluf(float x) { return x > 0.f ? x : expm1f(x); }
__device__ __forceinline__ unsigned fenc(float f) {
    unsigned b = __float_as_uint(f);
    return (b & 0x80000000u) ? ~b : (b | 0x80000000u);
}
__device__ __forceinline__ float fdec(unsigned u) {
    return (u & 0x80000000u) ? __uint_as_float(u & 0x7fffffffu) : __uint_as_float(~u);
}

// ---------------- 1) adjacency -> bitmask ----------------
__global__ void k_mask(const int* __restrict__ adj) {
    int word = blockIdx.x * 8 + (threadIdx.x >> 5);
    int lane = threadIdx.x & 31;
    size_t idx = (size_t)word * 32 + lane;
    int a = adj[idx];
    unsigned b = __ballot_sync(0xffffffffu, a > 0);
    if (lane == 0) ((unsigned*)g_mask)[word] = b;
}

// ---------------- 2) Wh1 = x @ W1[h]  + fused src/dst dots + dmax atomic ----------------
__global__ __launch_bounds__(256) void k_gemm1(const float* __restrict__ x,
                                               const float* __restrict__ W1,
                                               const float* __restrict__ alpha1) {
    const int h = blockIdx.y;
    const int m0 = blockIdx.x * 128;
    __shared__ float As[128][36];
    __shared__ float Bs[32][68];
    __shared__ float sal[2 * FH];
    const float* W = W1 + (size_t)h * FIN * FH;
    int tid = threadIdx.x, lane = tid & 31, warp = tid >> 5;
    int l4 = lane >> 2, lm4 = lane & 3;
    int wm = warp * 16;
    if (tid < 2 * FH) sal[tid] = alpha1[h * 2 * FH + tid];

    float d[8][4];
#pragma unroll
    for (int nt = 0; nt < 8; nt++)
#pragma unroll
        for (int i = 0; i < 4; i++) d[nt][i] = 0.f;

    for (int k0 = 0; k0 < FIN; k0 += 32) {
#pragma unroll
        for (int i = 0; i < 4; i++) {
            int idx = tid + i * 256;
            int row = idx >> 3, c = (idx & 7) * 4;
            float4 v = *(const float4*)&x[(size_t)(m0 + row) * FIN + k0 + c];
            *(float4*)&As[row][c] = v;
        }
#pragma unroll
        for (int i = 0; i < 2; i++) {
            int idx = tid + i * 256;
            int row = idx >> 4, c = (idx & 15) * 4;
            float4 v = *(const float4*)&W[(size_t)(k0 + row) * FH + c];
            *(float4*)&Bs[row][c] = v;
        }
        __syncthreads();
#pragma unroll
        for (int kk = 0; kk < 32; kk += 8) {
            float af[4];
            af[0] = As[wm + l4][kk + lm4];
            af[1] = As[wm + l4 + 8][kk + lm4];
            af[2] = As[wm + l4][kk + lm4 + 4];
            af[3] = As[wm + l4 + 8][kk + lm4 + 4];
            uint32_t ahi[4], alo[4];
#pragma unroll
            for (int i = 0; i < 4; i++) tf32_split(af[i], ahi[i], alo[i]);
#pragma unroll
            for (int nt = 0; nt < 8; nt++) {
                float bf[2];
                bf[0] = Bs[kk + lm4][nt * 8 + l4];
                bf[1] = Bs[kk + lm4 + 4][nt * 8 + l4];
                uint32_t bhi[2], blo[2];
                tf32_split(bf[0], bhi[0], blo[0]);
                tf32_split(bf[1], bhi[1], blo[1]);
                mma_tf32(d[nt], ahi, bhi);
                mma_tf32(d[nt], alo, bhi);
                mma_tf32(d[nt], ahi, blo);
            }
        }
        __syncthreads();
    }
    // store Wh
#pragma unroll
    for (int nt = 0; nt < 8; nt++) {
        int r0 = m0 + wm + l4, c = nt * 8 + 2 * lm4;
        g_Wh1[h][r0][c]     = d[nt][0];
        g_Wh1[h][r0][c + 1] = d[nt][1];
        g_Wh1[h][r0 + 8][c]     = d[nt][2];
        g_Wh1[h][r0 + 8][c + 1] = d[nt][3];
    }
    // fused src/dst dots
    float s0 = 0.f, dv0 = 0.f, s1 = 0.f, dv1 = 0.f;
#pragma unroll
    for (int nt = 0; nt < 8; nt++) {
        int c = nt * 8 + 2 * lm4;
        s0  += d[nt][0] * sal[c] + d[nt][1] * sal[c + 1];
        dv0 += d[nt][0] * sal[FH + c] + d[nt][1] * sal[FH + c + 1];
        s1  += d[nt][2] * sal[c] + d[nt][3] * sal[c + 1];
        dv1 += d[nt][2] * sal[FH + c] + d[nt][3] * sal[FH + c + 1];
    }
#pragma unroll
    for (int o = 1; o <= 2; o <<= 1) {
        s0 += __shfl_xor_sync(0xffffffffu, s0, o);
        dv0 += __shfl_xor_sync(0xffffffffu, dv0, o);
        s1 += __shfl_xor_sync(0xffffffffu, s1, o);
        dv1 += __shfl_xor_sync(0xffffffffu, dv1, o);
    }
    int r0 = m0 + wm + l4;
    if (lm4 == 0) {
        g_src1[h][r0] = s0; g_dst1[h][r0] = dv0;
        g_src1[h][r0 + 8] = s1; g_dst1[h][r0 + 8] = dv1;
    }
    float dm = (lm4 == 0) ? fmaxf(dv0, dv1) : -3e38f;
#pragma unroll
    for (int o = 16; o; o >>= 1) dm = fmaxf(dm, __shfl_xor_sync(0xffffffffu, dm, o));
    if (lane == 0) atomicMax(&g_dmax1u[h], fenc(dm));
}

// ---------------- 3) V1 -> fp16 B-fragment layout ----------------
__global__ __launch_bounds__(256) void k_vprep1() {
    int idx = blockIdx.x * 256 + threadIdx.x;   // 4*512*64 threads
    int n = idx & 63;
    int k16 = (idx >> 6) & 511;
    int h = idx >> 15;
    const float* W = &g_Wh1[h][k16 * 16][0];
    uint32_t o[8];
#pragma unroll
    for (int lm = 0; lm < 4; lm++) {
        float p0 = W[(2 * lm) * FH + n];
        float p1 = W[(2 * lm + 1) * FH + n];
        float p8 = W[(2 * lm + 8) * FH + n];
        float p9 = W[(2 * lm + 9) * FH + n];
        o[lm * 2 + 0] = packh2(p1, p0);
        o[lm * 2 + 1] = packh2(p9, p8);
    }
    uint32_t* dst = &gV1h[h][k16][n][0][0];
    *(uint4*)dst = make_uint4(o[0], o[1], o[2], o[3]);
    *(uint4*)(dst + 4) = make_uint4(o[4], o[5], o[6], o[7]);
}

// ---------------- 4) layer-1 fp16 tensor-core attention (split-K 2) ----------------
__global__ __launch_bounds__(256, 2) void k_att1() {
    const int h = blockIdx.y;
    const int tid = threadIdx.x, lane = tid & 31, warp = tid >> 5;
    const int wt = warp >> 1, ks = warp & 1;
    const int l4 = lane >> 2, lm = lane & 3;
    const int row0 = blockIdx.x * 128 + wt * 32;
    __shared__ uint4 sv4[256];            // 4 KB: two k16 V tiles
    __shared__ float red[4][32][68];      // ks=1 partials

    const float Dmax = fdec(g_dmax1u[h]);
    float a1[4], a2[4];
    int rows[4];
#pragma unroll
    for (int f = 0; f < 4; f++) {
        int r = row0 + l4 + f * 8;
        rows[f] = r;
        float s = g_src1[h][r];
        float v = s + Dmax;
        float mub = fmaxf(v, 0.2f * v);
        a1[f] = (s - mub) * LOG2E;
        a2[f] = (0.2f * s - mub) * LOG2E;
    }
    float d[2][8][4];
#pragma unroll
    for (int fr = 0; fr < 2; fr++)
#pragma unroll
        for (int nt = 0; nt < 8; nt++)
#pragma unroll
            for (int i = 0; i < 4; i++) d[fr][nt][i] = 0.f;
    float srow[4] = {0.f, 0.f, 0.f, 0.f};

    const uint4* Vb = (const uint4*)&gV1h[h][0][0][0][0];
    const int shbase = ks * 16 + 2 * lm;

    for (int i = 0; i < 256; i++) {
        __syncthreads();
        sv4[tid] = Vb[i * 256 + tid];
        __syncthreads();
        int k16 = 2 * i + ks;
        float2 dA = *(const float2*)&g_dst1[h][k16 * 16 + 2 * lm];
        float2 dB = *(const float2*)&g_dst1[h][k16 * 16 + 2 * lm + 8];
        float b1x = dA.x * LOG2E, b1y = dA.x * (0.2f * LOG2E);
        float b2x = dA.y * LOG2E, b2y = dA.y * (0.2f * LOG2E);
        float b3x = dB.x * LOG2E, b3y = dB.x * (0.2f * LOG2E);
        float b4x = dB.y * LOG2E, b4y = dB.y * (0.2f * LOG2E);
        uint32_t A[2][4];
#pragma unroll
        for (int f = 0; f < 4; f++) {
            unsigned wv = g_mask[rows[f]][i] >> shbase;
            float p0 = ex2f(fmaxf(a1[f] + b1x, a2[f] + b1y));
            float p1 = ex2f(fmaxf(a1[f] + b2x, a2[f] + b2y));
            float p8 = ex2f(fmaxf(a1[f] + b3x, a2[f] + b3y));
            float p9 = ex2f(fmaxf(a1[f] + b4x, a2[f] + b4y));
            p0 = __uint_as_float(__float_as_uint(p0) & (0u - (wv & 1u)));
            p1 = __uint_as_float(__float_as_uint(p1) & (0u - ((wv >> 1) & 1u)));
            p8 = __uint_as_float(__float_as_uint(p8) & (0u - ((wv >> 8) & 1u)));
            p9 = __uint_as_float(__float_as_uint(p9) & (0u - ((wv >> 9) & 1u)));
            srow[f] += (p0 + p1) + (p8 + p9);
            A[f >> 1][0 + (f & 1)] = packh2(p1, p0);
            A[f >> 1][2 + (f & 1)] = packh2(p9, p8);
        }
        const uint32_t* svp = (const uint32_t*)sv4 + ks * 512;
#pragma unroll
        for (int nt = 0; nt < 8; nt++) {
            uint2 b = *(const uint2*)&svp[((nt * 8 + l4) * 4 + lm) * 2];
            mma_f16(d[0][nt], A[0], b.x, b.y);
            mma_f16(d[1][nt], A[1], b.x, b.y);
        }
    }
    if (ks == 1) {
#pragma unroll
        for (int fr = 0; fr < 2; fr++)
#pragma unroll
            for (int nt = 0; nt < 8; nt++)
#pragma unroll
                for (int i = 0; i < 4; i++)
                    red[wt][lane][(fr * 8 + nt) * 4 + i] = d[fr][nt][i];
#pragma unroll
        for (int f = 0; f < 4; f++) red[wt][lane][64 + f] = srow[f];
    }
    __syncthreads();
    if (ks == 0) {
#pragma unroll
        for (int fr = 0; fr < 2; fr++)
#pragma unroll
            for (int nt = 0; nt < 8; nt++)
#pragma unroll
                for (int i = 0; i < 4; i++)
                    d[fr][nt][i] += red[wt][lane][(fr * 8 + nt) * 4 + i];
#pragma unroll
        for (int f = 0; f < 4; f++) {
            srow[f] += red[wt][lane][64 + f];
            srow[f] += __shfl_xor_sync(0xffffffffu, srow[f], 1);
            srow[f] += __shfl_xor_sync(0xffffffffu, srow[f], 2);
            srow[f] = 1.0f / srow[f];
        }
#pragma unroll
        for (int fr = 0; fr < 2; fr++) {
            int r0 = row0 + l4 + fr * 16;
#pragma unroll
            for (int nt = 0; nt < 8; nt++) {
                int col = h * FH + nt * 8 + lm * 2;
                float x0 = eluf(d[fr][nt][0] * srow[fr * 2]);
                float x1 = eluf(d[fr][nt][1] * srow[fr * 2]);
                float y0 = eluf(d[fr][nt][2] * srow[fr * 2 + 1]);
                float y1 = eluf(d[fr][nt][3] * srow[fr * 2 + 1]);
                *(float2*)&g_h1[r0][col] = make_float2(x0, x1);
                *(float2*)&g_h1[r0 + 8][col] = make_float2(y0, y1);
            }
        }
    }
}

// ---------------- 5) Wh2 = h1 @ W2 (+ src2/dst2 + dmax2) ----------------
__global__ __launch_bounds__(256) void k_gemm2(const float* __restrict__ W2,
                                               const float* __restrict__ alpha2) {
    __shared__ float sW[256][21];
    __shared__ float sa[40];
    __shared__ float sdm[8];
    int tid = threadIdx.x;
    for (int q = tid; q < 256 * NCLS; q += 256) sW[q / NCLS][q % NCLS] = W2[q];
    if (tid < 40) sa[tid] = alpha2[tid];
    __syncthreads();
    int lane = tid & 31, warp = tid >> 5;
    int row = blockIdx.x * 8 + warp;
    float acc[NCLS];
#pragma unroll
    for (int c = 0; c < NCLS; c++) acc[c] = 0.f;
    for (int k = lane; k < 256; k += 32) {
        float hv = g_h1[row][k];
#pragma unroll
        for (int c = 0; c < NCLS; c++) acc[c] += hv * sW[k][c];
    }
#pragma unroll
    for (int c = 0; c < NCLS; c++)
#pragma unroll
        for (int o = 16; o; o >>= 1) acc[c] += __shfl_xor_sync(0xffffffffu, acc[c], o);
    if (lane == 0) {
        float s = 0.f, dv = 0.f;
#pragma unroll
        for (int c = 0; c < NCLS; c++) {
            g_Wh2[row][c] = acc[c];
            s += acc[c] * sa[c];
            dv += acc[c] * sa[NCLS + c];
        }
        g_src2[row] = s; g_dst2[row] = dv;
        sdm[warp] = dv;
    }
    __syncthreads();
    if (tid == 0) {
        float m = sdm[0];
#pragma unroll
        for (int i = 1; i < 8; i++) m = fmaxf(m, sdm[i]);
        atomicMax(&g_dmax2u[0], fenc(m));
    }
}

// ---------------- 6) V2 -> fp16 B-fragment layout (24-col padded) ----------------
__global__ __launch_bounds__(256) void k_vprep2() {
    int idx = blockIdx.x * 256 + threadIdx.x;    // 512*24 threads
    if (idx >= 512 * 24) return;
    int n = idx % 24;
    int k16 = idx / 24;
    uint32_t o[8];
#pragma unroll
    for (int lm = 0; lm < 4; lm++) {
        float p0 = 0.f, p1 = 0.f, p8 = 0.f, p9 = 0.f;
        if (n < NCLS) {
            p0 = g_Wh2[k16 * 16 + 2 * lm][n];
            p1 = g_Wh2[k16 * 16 + 2 * lm + 1][n];
            p8 = g_Wh2[k16 * 16 + 2 * lm + 8][n];
            p9 = g_Wh2[k16 * 16 + 2 * lm + 9][n];
        }
        o[lm * 2 + 0] = packh2(p1, p0);
        o[lm * 2 + 1] = packh2(p9, p8);
    }
    uint32_t* dst = &gV2h[k16][n][0][0];
    *(uint4*)dst = make_uint4(o[0], o[1], o[2], o[3]);
    *(uint4*)(dst + 4) = make_uint4(o[4], o[5], o[6], o[7]);
}

// ---------------- 7) layer-2 fp16 attention (split-K 8) -> out ----------------
__global__ __launch_bounds__(256) void k_att2(float* __restrict__ out) {
    const int tid = threadIdx.x, lane = tid & 31, warp = tid >> 5;
    const int row0 = blockIdx.x * 32;
    const int l4 = lane >> 2, lm = lane & 3;
    __shared__ float red[8][32][28];

    const float Dmax = fdec(g_dmax2u[0]);
    float a1[4], a2[4];
    int rows[4];
#pragma unroll
    for (int f = 0; f < 4; f++) {
        int r = row0 + l4 + f * 8;
        rows[f] = r;
        float s = g_src2[r];
        float v = s + Dmax;
        float mub = fmaxf(v, 0.2f * v);
        a1[f] = (s - mub) * LOG2E;
        a2[f] = (0.2f * s - mub) * LOG2E;
    }
    float d[2][3][4];
#pragma unroll
    for (int fr = 0; fr < 2; fr++)
#pragma unroll
        for (int nt = 0; nt < 3; nt++)
#pragma unroll
            for (int i = 0; i < 4; i++) d[fr][nt][i] = 0.f;
    float srow[4] = {0.f, 0.f, 0.f, 0.f};
    const int shbase = (warp & 1) * 16 + 2 * lm;

    for (int i = 0; i < 64; i++) {
        int k16 = warp + 8 * i;
        int w = k16 >> 1;
        float2 dA = *(const float2*)&g_dst2[k16 * 16 + 2 * lm];
        float2 dB = *(const float2*)&g_dst2[k16 * 16 + 2 * lm + 8];
        float b1x = dA.x * LOG2E, b1y = dA.x * (0.2f * LOG2E);
        float b2x = dA.y * LOG2E, b2y = dA.y * (0.2f * LOG2E);
        float b3x = dB.x * LOG2E, b3y = dB.x * (0.2f * LOG2E);
        float b4x = dB.y * LOG2E, b4y = dB.y * (0.2f * LOG2E);
        uint32_t A[2][4];
#pragma unroll
        for (int f = 0; f < 4; f++) {
            unsigned wv = g_mask[rows[f]][w] >> shbase;
            float p0 = ex2f(fmaxf(a1[f] + b1x, a2[f] + b1y));
            float p1 = ex2f(fmaxf(a1[f] + b2x, a2[f] + b2y));
            float p8 = ex2f(fmaxf(a1[f] + b3x, a2[f] + b3y));
            float p9 = ex2f(fmaxf(a1[f] + b4x, a2[f] + b4y));
            p0 = __uint_as_float(__float_as_uint(p0) & (0u - (wv & 1u)));
            p1 = __uint_as_float(__float_as_uint(p1) & (0u - ((wv >> 1) & 1u)));
            p8 = __uint_as_float(__float_as_uint(p8) & (0u - ((wv >> 8) & 1u)));
            p9 = __uint_as_float(__float_as_uint(p9) & (0u - ((wv >> 9) & 1u)));
            srow[f] += (p0 + p1) + (p8 + p9);
            A[f >> 1][0 + (f & 1)] = packh2(p1, p0);
            A[f >> 1][2 + (f & 1)] = packh2(p9, p8);
        }
#pragma unroll
        for (int nt = 0; nt < 3; nt++) {
            uint2 b = *(const uint2*)&gV2h[k16][nt * 8 + l4][lm][0];
            mma_f16(d[0][nt], A[0], b.x, b.y);
            mma_f16(d[1][nt], A[1], b.x, b.y);
        }
    }
#pragma unroll
    for (int fr = 0; fr < 2; fr++)
#pragma unroll
        for (int nt = 0; nt < 3; nt++)
#pragma unroll
            for (int i = 0; i < 4; i++)
                red[warp][lane][(fr * 3 + nt) * 4 + i] = d[fr][nt][i];
#pragma unroll
    for (int f = 0; f < 4; f++) red[warp][lane][24 + f] = srow[f];
    __syncthreads();
    if (warp == 0) {
        float dd[2][3][4], ss[4];
#pragma unroll
        for (int fr = 0; fr < 2; fr++)
#pragma unroll
            for (int nt = 0; nt < 3; nt++)
#pragma unroll
                for (int i = 0; i < 4; i++) {
                    float s = 0.f;
#pragma unroll
                    for (int w = 0; w < 8; w++) s += red[w][lane][(fr * 3 + nt) * 4 + i];
                    dd[fr][nt][i] = s;
                }
#pragma unroll
        for (int f = 0; f < 4; f++) {
            float s = 0.f;
#pragma unroll
            for (int w = 0; w < 8; w++) s += red[w][lane][24 + f];
            s += __shfl_xor_sync(0xffffffffu, s, 1);
            s += __shfl_xor_sync(0xffffffffu, s, 2);
            ss[f] = 1.0f / s;
        }
#pragma unroll
        for (int fr = 0; fr < 2; fr++) {
            int r0 = row0 + l4 + fr * 16;
#pragma unroll
            for (int nt = 0; nt < 3; nt++) {
                int col = nt * 8 + lm * 2;
                if (col < NCLS) {
                    float x0 = eluf(dd[fr][nt][0] * ss[fr * 2]);
                    float x1 = eluf(dd[fr][nt][1] * ss[fr * 2]);
                    float y0 = eluf(dd[fr][nt][2] * ss[fr * 2 + 1]);
                    float y1 = eluf(dd[fr][nt][3] * ss[fr * 2 + 1]);
                    *(float2*)&out[(size_t)r0 * NCLS + col] = make_float2(x0, x1);
                    *(float2*)&out[(size_t)(r0 + 8) * NCLS + col] = make_float2(y0, y1);
                }
            }
        }
    }
}

// ---------------- launch ----------------
extern "C" void kernel_launch(void* const* d_in, const int* in_sizes, int n_in,
                              void* d_out, int out_size) {
    const float* x      = (const float*)d_in[0];
    const int*   adj    = (const int*)d_in[1];
    const float* W1     = (const float*)d_in[2];
    const float* alpha1 = (const float*)d_in[3];
    const float* W2     = (const float*)d_in[4];
    const float* alpha2 = (const float*)d_in[5];
    float* out = (float*)d_out;

    k_mask<<<(NN * (NN / 32)) / 8, 256>>>(adj);
    k_gemm1<<<dim3(NN / 128, NHEAD), 256>>>(x, W1, alpha1);
    k_vprep1<<<(NHEAD * (NN / 16) * FH) / 256, 256>>>();
    k_att1<<<dim3(NN / 128, NHEAD), 256>>>();           // 4th launch -> profiled
    k_gemm2<<<NN / 8, 256>>>(W2, alpha2);
    k_vprep2<<<(512 * 24 + 255) / 256, 256>>>();
    k_att2<<<NN / 32, 256>>>(out);
}